// round 8
// baseline (speedup 1.0000x reference)
#include <cuda_runtime.h>
#include <math.h>
#include <stdint.h>

#define NF 3000
#define NB 1500
#define RAD2 9.0f
#define INV_R (1.0f/3.0f)
#define CAP 256
#define EPSF 1e-8f
#define FOUR_OVER_PI 1.2732395447351628f

// ---------------- static device scratch ----------------
__device__ float g_p1[NF*3];
__device__ float g_feat0[NF*9];
__device__ int   g_fcnt[NF];
__device__ int   g_fidx[NF*64];
__device__ int   g_fbase[NF*64];
__device__ float g_fw8[NF*512];
__device__ int   g_bcnt[NF];
__device__ int   g_bidx[NF*64];
__device__ int   g_bbase[NF*64];
__device__ float g_bw8[NF*512];
__device__ float g_A0[9000*192];
__device__ float g_A[(size_t)9000*6144];
__device__ float g_Abox[NF*64];
__device__ float g_cf[9000*32];
__device__ float g_co[NF*32];
__device__ float g_oc[2*9000*64];
__device__ float g_od[9000*64];
__device__ float g_out1[9000*96];
__device__ float g_out2[9000*96];

// ---------------- packed f32x2 helpers ----------------
#define PACKF2(d, lo, hi)  asm("mov.b64 %0, {%1,%2};" : "=l"(d) : "f"(lo), "f"(hi))
#define FMAF2(acc, a, b)   asm("fma.rn.f32x2 %0, %1, %2, %0;" : "+l"(acc) : "l"(a), "l"(b))
#define UNPACKF2(lo, hi, v) asm("mov.b64 {%0,%1}, %2;" : "=f"(lo), "=f"(hi) : "l"(v))

// ---------------- geometry ----------------
__device__ __forceinline__ float sgnf(float v){ return (v>0.f)?1.f:((v<0.f)?-1.f:0.f); }

__device__ __forceinline__ void ball_to_cube(float x,float y,float z,float&obx,float&oby,float&obz){
    float sq = x*x+y*y+z*z;
    float norm = sqrtf(fmaxf(sq,EPSF));
    float xy_sq = x*x+y*y;
    bool polar = (1.25f*z*z) > xy_sq;
    float s_p = sqrtf(3.0f*norm/(norm+fabsf(z)+EPSF));
    float s_e = norm / sqrtf(fmaxf(xy_sq,EPSF));
    float cx = polar ? x*s_p : x*s_e;
    float cy = polar ? y*s_p : y*s_e;
    float cz = polar ? sgnf(z)*norm : 1.5f*z;
    float nxy = sqrtf(fmaxf(cx*cx+cy*cy,EPSF));
    bool xdom = fabsf(cy) <= fabsf(cx);
    float sx = (fabsf(cx) > EPSF) ? cx : 1.0f;
    float sy = (fabsf(cy) > EPSF) ? cy : 1.0f;
    float bx1 = sgnf(cx)*nxy;
    float by1 = bx1*FOUR_OVER_PI*atanf(cy/sx);
    float by2 = sgnf(cy)*nxy;
    float bx2 = by2*FOUR_OVER_PI*atanf(cx/sy);
    float bx = xdom ? bx1 : bx2;
    float by = xdom ? by1 : by2;
    if (cx*cx+cy*cy < EPSF){ bx=0.f; by=0.f; }
    if (sq < EPSF){ bx=0.f; by=0.f; cz=0.f; }
    obx=bx; oby=by; obz=cz;
}

// ---------------- prep ----------------
__global__ void prep_kernel(const float* __restrict__ p0,const float* __restrict__ v0,
                            const float* __restrict__ a,const float* __restrict__ other,
                            const float* __restrict__ v0e,
                            float* __restrict__ p1,float* __restrict__ feat0,
                            float* __restrict__ outState){
    int i = blockIdx.x*blockDim.x + threadIdx.x;
    if (i >= NF) return;
#pragma unroll
    for (int d=0; d<3; d++){
        float vv0 = v0[i*3+d];
        float v1  = vv0 + 0.1f*a[i*3+d];
        float pp1 = p0[i*3+d] + 0.1f*(vv0+v1)*0.5f;
        p1[i*3+d]        = pp1;
        feat0[i*9+d]     = v1;
        feat0[i*9+3+d]   = other[i*3+d];
        feat0[i*9+6+d]   = v0e[i*3+d];
        outState[i*3+d]  = v0e[i*3+d];
    }
}

// ---------------- neighbor search (256 thr): exact top-64, then base-sorted ----------------
__global__ void neigh_kernel(const float* __restrict__ pin, int Mp,
                             const float* __restrict__ pout,
                             const float* __restrict__ mask, int selfEx,
                             int* __restrict__ cntO, int* __restrict__ idxO,
                             int* __restrict__ baseO, float* __restrict__ w8O){
    __shared__ float cd2[CAP];
    __shared__ int   cid[CAP];
    __shared__ unsigned long long keys[CAP];
    __shared__ int scnt;
    __shared__ int   sM[64];
    __shared__ int   sB[64];
    __shared__ float sW8[64*8];
    __shared__ unsigned skey[64];
    int n = blockIdx.x, tid = threadIdx.x;
    float qx = pout[n*3], qy = pout[n*3+1], qz = pout[n*3+2];
    if (tid==0) scnt = 0;
    __syncthreads();
    for (int m = tid; m < Mp; m += blockDim.x){
        if (selfEx && m==n) continue;
        if (mask && !(mask[m] > 0.f)) continue;
        float dx = pin[m*3]-qx, dy = pin[m*3+1]-qy, dz = pin[m*3+2]-qz;
        float d2 = dx*dx + dy*dy + dz*dz;
        if (d2 <= RAD2){
            int p = atomicAdd(&scnt, 1);
            if (p < CAP){ cd2[p]=d2; cid[p]=m; }
        }
    }
    __syncthreads();
    int cn = min(scnt, CAP);
    for (int t = tid; t < CAP; t += blockDim.x)
        keys[t] = (t < cn) ? ((((unsigned long long)__float_as_uint(cd2[t]))<<32) | (unsigned)cid[t])
                           : 0xFFFFFFFFFFFFFFFFull;
    __syncthreads();
    for (int k = 2; k <= CAP; k <<= 1){
        for (int j = k>>1; j > 0; j >>= 1){
            if (tid < 128){
                int i = ((tid & ~(j-1)) << 1) | (tid & (j-1));
                int ixj = i | j;
                bool asc = ((i & k) == 0);
                unsigned long long av = keys[i], bv = keys[ixj];
                if ((av > bv) == asc){ keys[i]=bv; keys[ixj]=av; }
            }
            __syncthreads();
        }
    }
    int keep = min(cn, 64);
    if (tid==0) cntO[n] = keep;
    for (int t = tid; t < keep; t += blockDim.x){
        unsigned long long key = keys[t];
        int m = (int)(key & 0xFFFFFFFFull);
        float dx = pin[m*3]-qx, dy = pin[m*3+1]-qy, dz = pin[m*3+2]-qz;
        float ux = dx*INV_R, uy = dy*INV_R, uz = dz*INV_R;
        float r2 = ux*ux + uy*uy + uz*uz;
        float t1 = 1.f - r2;
        float win = fminf(fmaxf(t1*t1*t1, 0.f), 1.f);
        float bx, by, bz;
        ball_to_cube(ux, uy, uz, bx, by, bz);
        float cxx = fminf(fmaxf((bx*0.5f+0.5f)*3.f, 0.f), 3.f);
        float cyy = fminf(fmaxf((by*0.5f+0.5f)*3.f, 0.f), 3.f);
        float czz = fminf(fmaxf((bz*0.5f+0.5f)*3.f, 0.f), 3.f);
        int c0x = min((int)floorf(cxx), 2);
        int c0y = min((int)floorf(cyy), 2);
        int c0z = min((int)floorf(czz), 2);
        float fx = cxx - (float)c0x, fy = cyy - (float)c0y, fz = czz - (float)c0z;
        sM[t] = m;
        sB[t] = (c0x*4 + c0y)*4 + c0z;
        float gx[2] = {1.f-fx, fx}, gy[2] = {1.f-fy, fy}, gz[2] = {1.f-fz, fz};
        int jj = 0;
        for (int i2=0;i2<2;i2++) for (int j2=0;j2<2;j2++) for (int l2=0;l2<2;l2++)
            sW8[t*8 + (jj++)] = gx[i2]*gy[j2]*gz[l2]*win;
    }
    for (int t = tid; t < 64; t += blockDim.x)
        skey[t] = (t < keep) ? (unsigned)((sB[t] << 6) | t) : 0xFFFFFFFFu;
    __syncthreads();
    for (int k = 2; k <= 64; k <<= 1){
        for (int j = k>>1; j > 0; j >>= 1){
            if (tid < 32){
                int i = ((tid & ~(j-1)) << 1) | (tid & (j-1));
                int ixj = i | j;
                bool asc = ((i & k) == 0);
                unsigned av = skey[i], bv = skey[ixj];
                if ((av > bv) == asc){ skey[i]=bv; skey[ixj]=av; }
            }
            __syncthreads();
        }
    }
    for (int t = tid; t < keep; t += blockDim.x){
        int s = (int)(skey[t] & 63u);
        idxO[n*64+t]  = sM[s];
        baseO[n*64+t] = sB[s];
#pragma unroll
        for (int j=0;j<8;j++) w8O[n*512 + t*8 + j] = sW8[s*8 + j];
    }
}

__constant__ int c_coff[8] = {0,1,4,5,16,17,20,21};

// ---------------- scatter layer0 fluid (F=9): per-corner planes, sync-free ----------------
__global__ void scatter9(const float* __restrict__ feats,
                         const int* __restrict__ cnt, const int* __restrict__ nidx,
                         const int* __restrict__ nbase, const float* __restrict__ nw8,
                         float* __restrict__ A){
    __shared__ float planes[8*576];
    __shared__ float sfeat[64*9];
    __shared__ float sW[512];
    __shared__ int   sBase[64];
    __shared__ int   sIdx[64];
    int n = blockIdx.x, tid = threadIdx.x;
    int cn = cnt[n];
    for (int e = tid; e < 8*576; e += 96) planes[e] = 0.f;
    if (tid < cn){ sIdx[tid] = nidx[n*64+tid]; sBase[tid] = nbase[n*64+tid]; }
    for (int e = tid; e < cn*8; e += 96) sW[e] = nw8[n*512+e];
    __syncthreads();
    for (int e = tid; e < cn*9; e += 96){
        int k = e/9, f = e-k*9;
        sfeat[e] = feats[(size_t)sIdx[k]*9 + f];
    }
    __syncthreads();
    if (tid < 72){
        int j = tid/9, f = tid - j*9;
        int off = c_coff[j];
        float r = 0.f; int prevb = -1;
        for (int k = 0; k < cn; k++){
            int b = sBase[k];
            if (b != prevb){
                if (prevb >= 0) planes[j*576 + (prevb+off)*9 + f] += r;
                prevb = b; r = 0.f;
            }
            r += sW[k*8+j]*sfeat[k*9+f];
        }
        if (prevb >= 0) planes[j*576 + (prevb+off)*9 + f] += r;
    }
    __syncthreads();
    for (int e = tid; e < 576; e += 96){
        int l = e/9, f = e-l*9;
        int s = f/3, c = f-s*3;
        float v = 0.f;
#pragma unroll
        for (int j=0;j<8;j++) v += planes[j*576+e];
        A[(size_t)(n*3+s)*192 + l*3 + c] = v;
    }
}

// ---------------- scatter box (F=1): 8 queries per 64-thread block ----------------
__global__ void scatter1(const float* __restrict__ feats,
                         const int* __restrict__ cnt, const int* __restrict__ nidx,
                         const int* __restrict__ nbase, const float* __restrict__ nw8,
                         float* __restrict__ A){
    __shared__ float planes[8*8*64];
    __shared__ float sF[8*64];
    __shared__ float sW[8*512];
    __shared__ int   sBase[8*64];
    __shared__ int   sCn[8];
    int tid = threadIdx.x, nb = blockIdx.x;
    for (int e = tid; e < 8*8*64; e += 64) planes[e] = 0.f;
    for (int e = tid; e < 8*64; e += 64){
        int q = e>>6, k = e&63;
        int n = nb*8+q;
        if (k==0) sCn[q] = cnt[n];
        int cnq = cnt[n];
        if (k < cnq){ sBase[e] = nbase[n*64+k]; sF[e] = feats[nidx[n*64+k]]; }
    }
    for (int e = tid; e < 8*512; e += 64){
        int q = e>>9, r = e&511;
        sW[e] = nw8[(size_t)(nb*8+q)*512 + r];
    }
    __syncthreads();
    {
        int q = tid>>3, j = tid&7;
        int off = c_coff[j];
        int cnq = sCn[q];
        float r = 0.f; int prevb = -1;
        for (int k = 0; k < cnq; k++){
            int b = sBase[q*64+k];
            if (b != prevb){
                if (prevb >= 0) planes[(q*8+j)*64 + prevb+off] += r;
                prevb = b; r = 0.f;
            }
            r += sW[q*512 + k*8 + j]*sF[q*64+k];
        }
        if (prevb >= 0) planes[(q*8+j)*64 + prevb+off] += r;
    }
    __syncthreads();
    for (int e = tid; e < 512; e += 64){
        int q = e>>6, l = e&63;
        float v = 0.f;
#pragma unroll
        for (int j=0;j<8;j++) v += planes[(q*8+j)*64 + l];
        A[(size_t)(nb*8+q)*64 + l] = v;
    }
}

// ---------------- scatter (big): float4, register run-accumulation, fp32 A out ----------------
__global__ void scatter_big(const float* __restrict__ feats, int F, int C, int S,
                            const int* __restrict__ cnt, const int* __restrict__ nidx,
                            const int* __restrict__ nbase, const float* __restrict__ nw8,
                            float* __restrict__ A, int reluA){
    extern __shared__ float acc[];
    __shared__ int sIdx[64]; __shared__ int sBase[64]; __shared__ float sW[512];
    float4* acc4 = (float4*)acc;
    int n = blockIdx.x, tid = threadIdx.x, bd = blockDim.x;
    int F4 = F >> 2;
    int cn = cnt[n];
    for (int e = tid; e < 64*F4; e += bd) acc4[e] = make_float4(0.f,0.f,0.f,0.f);
    for (int e = tid; e < cn; e += bd){ sIdx[e] = nidx[n*64+e]; sBase[e] = nbase[n*64+e]; }
    for (int e = tid; e < cn*8; e += bd) sW[e] = nw8[n*512+e];
    __syncthreads();
    int f4 = tid;
    if (f4 < F4){
        float4 r[8];
        int prevb = -1;
        for (int k = 0; k < cn; k++){
            int b = sBase[k];
            if (b != prevb){
                if (prevb >= 0){
#pragma unroll
                    for (int j=0;j<8;j++){
                        int ai = (prevb + c_coff[j])*F4 + f4;
                        float4 t = acc4[ai];
                        t.x += r[j].x; t.y += r[j].y; t.z += r[j].z; t.w += r[j].w;
                        acc4[ai] = t;
                    }
                }
                prevb = b;
#pragma unroll
                for (int j=0;j<8;j++) r[j] = make_float4(0.f,0.f,0.f,0.f);
            }
            float4 fv = ((const float4*)(feats + (size_t)sIdx[k]*F))[f4];
            if (reluA){
                fv.x = fmaxf(fv.x,0.f); fv.y = fmaxf(fv.y,0.f);
                fv.z = fmaxf(fv.z,0.f); fv.w = fmaxf(fv.w,0.f);
            }
#pragma unroll
            for (int j=0;j<8;j++){
                float w = sW[k*8+j];
                r[j].x += w*fv.x; r[j].y += w*fv.y; r[j].z += w*fv.z; r[j].w += w*fv.w;
            }
        }
        if (prevb >= 0){
#pragma unroll
            for (int j=0;j<8;j++){
                int ai = (prevb + c_coff[j])*F4 + f4;
                float4 t = acc4[ai];
                t.x += r[j].x; t.y += r[j].y; t.z += r[j].z; t.w += r[j].w;
                acc4[ai] = t;
            }
        }
    }
    __syncthreads();
    int KC = 64*C;
    float4* A4 = (float4*)A;
    for (int e4 = tid; e4 < 64*F4; e4 += bd){
        int l = e4 / F4, fl = e4 - l*F4;
        int f = fl*4;
        int s = f / C, c = f - s*C;
        A4[(((size_t)(n*S+s))*KC + l*C + c) >> 2] = acc4[e4];
    }
}

// ---------------- packed-f32x2 GEMM: C[M,64] = A[M,K] @ B[K,64]; 128x64 tile, 128 thr ----------------
__global__ __launch_bounds__(128) void gemm_x2(const float* __restrict__ A,
                                               const float* __restrict__ B,
                                               float* __restrict__ Cc,
                                               int M, int K, int reluA){
    __shared__ float As[2][16][128];
    __shared__ float Bs[2][16][64];
    int tid = threadIdx.x;
    int bm = blockIdx.x * 128;
    int kLen = K / gridDim.y;
    int kBeg = blockIdx.y * kLen;
    int T = kLen >> 4;
    float* Cout = Cc + (size_t)blockIdx.y * M * 64;
    int tm = tid >> 3, tn = tid & 7;
    int arow = min(bm + tid, M-1);
    const float* Aptr = A + (size_t)arow*K + kBeg;
    int brow = tid >> 3, bcol = (tid & 7) * 8;
    const float* Bptr = B + (size_t)(kBeg + brow)*64 + bcol;

    float4 pa[4], pb[2];
#pragma unroll
    for (int q=0;q<4;q++) pa[q] = *(const float4*)(Aptr + q*4);
    pb[0] = *(const float4*)(Bptr);
    pb[1] = *(const float4*)(Bptr + 4);
    if (reluA){
#pragma unroll
        for (int q=0;q<4;q++){
            pa[q].x=fmaxf(pa[q].x,0.f); pa[q].y=fmaxf(pa[q].y,0.f);
            pa[q].z=fmaxf(pa[q].z,0.f); pa[q].w=fmaxf(pa[q].w,0.f);
        }
    }
#pragma unroll
    for (int q=0;q<4;q++){
        As[0][q*4+0][tid]=pa[q].x; As[0][q*4+1][tid]=pa[q].y;
        As[0][q*4+2][tid]=pa[q].z; As[0][q*4+3][tid]=pa[q].w;
    }
    *(float4*)&Bs[0][brow][bcol] = pb[0];
    *(float4*)&Bs[0][brow][bcol+4] = pb[1];
    __syncthreads();

    unsigned long long acc[8][4] = {};
    for (int t = 0; t < T; t++){
        int cb = t & 1;
        if (t+1 < T){
#pragma unroll
            for (int q=0;q<4;q++) pa[q] = *(const float4*)(Aptr + (size_t)(t+1)*16 + q*4);
            pb[0] = *(const float4*)(Bptr + (size_t)(t+1)*16*64);
            pb[1] = *(const float4*)(Bptr + (size_t)(t+1)*16*64 + 4);
            if (reluA){
#pragma unroll
                for (int q=0;q<4;q++){
                    pa[q].x=fmaxf(pa[q].x,0.f); pa[q].y=fmaxf(pa[q].y,0.f);
                    pa[q].z=fmaxf(pa[q].z,0.f); pa[q].w=fmaxf(pa[q].w,0.f);
                }
            }
        }
#pragma unroll
        for (int kk = 0; kk < 16; kk++){
            float4 a0 = *(const float4*)&As[cb][kk][tm*8];
            float4 a1 = *(const float4*)&As[cb][kk][tm*8+4];
            ulonglong2 b01 = *(const ulonglong2*)&Bs[cb][kk][tn*8];
            ulonglong2 b23 = *(const ulonglong2*)&Bs[cb][kk][tn*8+4];
            unsigned long long bp0 = b01.x, bp1 = b01.y, bp2 = b23.x, bp3 = b23.y;
            float av[8] = {a0.x,a0.y,a0.z,a0.w,a1.x,a1.y,a1.z,a1.w};
#pragma unroll
            for (int i=0;i<8;i++){
                unsigned long long ad;
                PACKF2(ad, av[i], av[i]);
                FMAF2(acc[i][0], ad, bp0);
                FMAF2(acc[i][1], ad, bp1);
                FMAF2(acc[i][2], ad, bp2);
                FMAF2(acc[i][3], ad, bp3);
            }
        }
        if (t+1 < T){
            int nb2 = cb ^ 1;
#pragma unroll
            for (int q=0;q<4;q++){
                As[nb2][q*4+0][tid]=pa[q].x; As[nb2][q*4+1][tid]=pa[q].y;
                As[nb2][q*4+2][tid]=pa[q].z; As[nb2][q*4+3][tid]=pa[q].w;
            }
            *(float4*)&Bs[nb2][brow][bcol] = pb[0];
            *(float4*)&Bs[nb2][brow][bcol+4] = pb[1];
            __syncthreads();
        }
    }
#pragma unroll
    for (int i=0;i<8;i++){
        int r = bm + tm*8 + i;
        if (r >= M) continue;
#pragma unroll
        for (int jp=0;jp<4;jp++){
            float lo, hi;
            UNPACKF2(lo, hi, acc[i][jp]);
            float2 v2 = make_float2(lo, hi);
            *(float2*)&Cout[(size_t)r*64 + tn*8 + jp*2] = v2;
        }
    }
}

// ---------------- fp32 GEMM N=32 (layer 0) ----------------
__global__ void gemm32(const float* __restrict__ A, const float* __restrict__ B,
                       float* __restrict__ Cc, int M, int N, int K){
    __shared__ float As[16][64];
    __shared__ float Bs[16][64];
    int tid = threadIdx.x;
    int bm = blockIdx.x * 64;
    int tm = tid >> 4, tn = tid & 15;
    float accv[4][4] = {};
    int arow = bm + (tid >> 2);
    int akq  = (tid & 3) * 4;
    int brow = tid >> 4;
    int bcol = (tid & 15) * 4;
    for (int k0 = 0; k0 < K; k0 += 16){
        float4 a4 = make_float4(0.f,0.f,0.f,0.f);
        if (arow < M) a4 = *(const float4*)(A + (size_t)arow*K + k0 + akq);
        float4 b4 = make_float4(0.f,0.f,0.f,0.f);
        if (bcol < N) b4 = *(const float4*)(B + (size_t)(k0+brow)*N + bcol);
        __syncthreads();
        int lr = tid >> 2;
        As[akq+0][lr] = a4.x; As[akq+1][lr] = a4.y; As[akq+2][lr] = a4.z; As[akq+3][lr] = a4.w;
        *(float4*)&Bs[brow][bcol] = b4;
        __syncthreads();
#pragma unroll
        for (int kk = 0; kk < 16; kk++){
            float4 av = *(const float4*)&As[kk][tm*4];
            float4 bv = *(const float4*)&Bs[kk][tn*4];
            float ar[4] = {av.x, av.y, av.z, av.w};
            float brr[4] = {bv.x, bv.y, bv.z, bv.w};
#pragma unroll
            for (int i=0;i<4;i++)
#pragma unroll
                for (int j=0;j<4;j++) accv[i][j] += ar[i]*brr[j];
        }
    }
#pragma unroll
    for (int i=0;i<4;i++){
        int r = bm + tm*4 + i;
        if (r >= M) continue;
#pragma unroll
        for (int j=0;j<4;j++){
            int c = tn*4 + j;
            if (c < N) Cc[(size_t)r*N + c] = accv[i][j];
        }
    }
}

// ---------------- dot kernel (fp32, N<=3) ----------------
__global__ void dotn_kernel(const float* __restrict__ A, const float* __restrict__ B,
                            float* __restrict__ Cc, int M, int N, int K, int reluA){
    extern __shared__ float sBv[];
    int tid = threadIdx.x;
    for (int i = tid; i < K*N; i += blockDim.x) sBv[i] = B[i];
    __syncthreads();
    int w = tid >> 5, lane = tid & 31;
    int r = blockIdx.x * 8 + w;
    if (r >= M) return;
    float a0=0.f, a1=0.f, a2=0.f;
    const float* ap = A + (size_t)r*K;
    for (int k = lane; k < K; k += 32){
        float av = ap[k];
        if (reluA) av = fmaxf(av, 0.f);
        a0 += av * sBv[k*N+0];
        if (N > 1) a1 += av * sBv[k*N+1];
        if (N > 2) a2 += av * sBv[k*N+2];
    }
    for (int off=16; off; off>>=1){
        a0 += __shfl_down_sync(0xffffffffu, a0, off);
        a1 += __shfl_down_sync(0xffffffffu, a1, off);
        a2 += __shfl_down_sync(0xffffffffu, a2, off);
    }
    if (lane == 0){
        Cc[(size_t)r*N+0] = a0;
        if (N > 1) Cc[(size_t)r*N+1] = a1;
        if (N > 2) Cc[(size_t)r*N+2] = a2;
    }
}

// ---------------- elementwise ----------------
__global__ void combine0_kernel(const float* __restrict__ co, const float* __restrict__ cf,
                                const float* __restrict__ feat0,
                                const float* __restrict__ b0o, const float* __restrict__ b0f,
                                const float* __restrict__ wdf, const float* __restrict__ bdf,
                                float* __restrict__ out){
    int e = blockIdx.x*blockDim.x + threadIdx.x;
    if (e >= 9000*96) return;
    int row = e / 96, o = e - row*96;
    int n = row / 3;
    float v;
    if (o < 32) v = co[n*32+o] + b0o[o];
    else if (o < 64) v = cf[(size_t)row*32 + (o-32)] + b0f[o-32];
    else {
        int oo = o - 64;
        v = bdf[oo];
        for (int c=0;c<3;c++) v += feat0[row*3+c]*wdf[c*32+oo];
    }
    out[e] = v;
}

__global__ void combine_kernel(const float* __restrict__ oc, const float* __restrict__ oc2,
                               const float* __restrict__ od,
                               const float* __restrict__ bc, const float* __restrict__ bd,
                               const float* __restrict__ prev, float* __restrict__ out, int C){
    int e = blockIdx.x*blockDim.x + threadIdx.x;
    if (e >= 9000*C) return;
    int o = e % C;
    float v = oc[e] + bc[o] + od[e] + bd[o];
    if (oc2)  v += oc2[e];
    if (prev) v += prev[e];
    out[e] = v;
}

__global__ void final_kernel(const float* __restrict__ out4, const float* __restrict__ p1,
                             const float* __restrict__ p0, float* __restrict__ dout){
    int e = blockIdx.x*blockDim.x + threadIdx.x;
    if (e >= NF*3) return;
    int n = e/3, d = e - n*3;
    float pc0 = out4[(n*3+0)*3+d] * 0.25f * (1.0f/16.0f);
    float pc1 = out4[(n*3+1)*3+d] * 0.25f;
    float pc2 = out4[(n*3+2)*3+d] * 0.25f;
    float p_c = p1[e] + pc0;
    dout[e] = p_c;
    dout[9000 + e] = (p_c - p0[e]) / 0.1f;
    dout[18000 + n*6 + d]     = pc1;
    dout[18000 + n*6 + 3 + d] = pc2;
}

// ---------------- launch ----------------
extern "C" void kernel_launch(void* const* d_in, const int* in_sizes, int n_in,
                              void* d_out, int out_size){
    const float* v0e  = (const float*)d_in[1];
    const float* p0   = (const float*)d_in[2];
    const float* v0   = (const float*)d_in[3];
    const float* a    = (const float*)d_in[4];
    const float* other= (const float*)d_in[5];
    const float* box  = (const float*)d_in[6];
    const float* boxf = (const float*)d_in[7];
    const float* bmask= (const float*)d_in[9];
    const float* k0f  = (const float*)d_in[10];
    const float* b0f  = (const float*)d_in[11];
    const float* k0o  = (const float*)d_in[12];
    const float* b0o  = (const float*)d_in[13];
    const float* wdf  = (const float*)d_in[14];
    const float* bdf  = (const float*)d_in[15];
    const float *kc[4], *bcp[4], *wd[4], *bdp[4];
    if (in_sizes[18] == 262144){
        for (int i=0;i<4;i++){
            kc[i]=(const float*)d_in[16+2*i]; bcp[i]=(const float*)d_in[17+2*i];
            wd[i]=(const float*)d_in[24+2*i]; bdp[i]=(const float*)d_in[25+2*i];
        }
    } else {
        for (int i=0;i<4;i++){
            kc[i]=(const float*)d_in[16+4*i]; bcp[i]=(const float*)d_in[17+4*i];
            wd[i]=(const float*)d_in[18+4*i]; bdp[i]=(const float*)d_in[19+4*i];
        }
    }
    float* dout = (float*)d_out;

    float *p1, *feat0, *A0, *A, *Abox, *cfb, *cob, *ocb, *odb, *o1, *o2, *fw8, *bw8;
    int *fcnt, *fidx, *fbase, *bcnt, *bidx, *bbase;
    cudaGetSymbolAddress((void**)&p1, g_p1);
    cudaGetSymbolAddress((void**)&feat0, g_feat0);
    cudaGetSymbolAddress((void**)&A0, g_A0);
    cudaGetSymbolAddress((void**)&A, g_A);
    cudaGetSymbolAddress((void**)&Abox, g_Abox);
    cudaGetSymbolAddress((void**)&cfb, g_cf);
    cudaGetSymbolAddress((void**)&cob, g_co);
    cudaGetSymbolAddress((void**)&ocb, g_oc);
    cudaGetSymbolAddress((void**)&odb, g_od);
    cudaGetSymbolAddress((void**)&o1, g_out1);
    cudaGetSymbolAddress((void**)&o2, g_out2);
    cudaGetSymbolAddress((void**)&fw8, g_fw8);
    cudaGetSymbolAddress((void**)&bw8, g_bw8);
    cudaGetSymbolAddress((void**)&fcnt, g_fcnt);
    cudaGetSymbolAddress((void**)&fidx, g_fidx);
    cudaGetSymbolAddress((void**)&fbase, g_fbase);
    cudaGetSymbolAddress((void**)&bcnt, g_bcnt);
    cudaGetSymbolAddress((void**)&bidx, g_bidx);
    cudaGetSymbolAddress((void**)&bbase, g_bbase);

    cudaFuncSetAttribute(scatter_big, cudaFuncAttributeMaxDynamicSharedMemorySize, 80000);
    cudaFuncSetAttribute(dotn_kernel, cudaFuncAttributeMaxDynamicSharedMemorySize, 50000);

    prep_kernel<<<(NF+127)/128, 128>>>(p0, v0, a, other, v0e, p1, feat0, dout + 36000);
    neigh_kernel<<<NF, 256>>>(p1, NF, p1, nullptr, 1, fcnt, fidx, fbase, fw8);
    neigh_kernel<<<NF, 256>>>(box, NB, p1, bmask, 0, bcnt, bidx, bbase, bw8);

    // layer 0
    scatter9<<<NF, 96>>>(feat0, fcnt, fidx, fbase, fw8, A0);
    gemm32<<<(9000+63)/64, 256>>>(A0, k0f, cfb, 9000, 32, 192);
    scatter1<<<NF/8, 64>>>(boxf, bcnt, bidx, bbase, bw8, Abox);
    gemm32<<<(3000+63)/64, 256>>>(Abox, k0o, cob, 3000, 32, 64);
    combine0_kernel<<<(9000*96+255)/256, 256>>>(cob, cfb, feat0, b0o, b0f, wdf, bdf, o1);

    int Cin[4] = {96, 64, 64, 64};
    float* cur = o1; float* nxt = o2;
    for (int i=0;i<4;i++){
        int ci = Cin[i];
        int F = 3*ci, F4 = F/4;
        int K = 64*ci;
        int bD = ((F4 + 31)/32)*32;
        scatter_big<<<NF, bD, (size_t)64*F*4>>>(cur, F, ci, 3, fcnt, fidx, fbase, fw8, A, 1);
        if (i < 3){
            gemm_x2<<<dim3(71,2), 128>>>(A,  kc[i], ocb, 9000, K, 0);
            gemm_x2<<<dim3(71,1), 128>>>(cur, wd[i], odb, 9000, ci, 1);
            combine_kernel<<<(9000*64+255)/256, 256>>>(ocb, ocb + (size_t)9000*64, odb,
                bcp[i], bdp[i], (i==1||i==2) ? cur : nullptr, nxt, 64);
        } else {
            dotn_kernel<<<(9000+7)/8, 256, (size_t)K*3*4>>>(A,  kc[3], ocb, 9000, 3, K, 0);
            dotn_kernel<<<(9000+7)/8, 256, (size_t)ci*3*4>>>(cur, wd[3], odb, 9000, 3, ci, 1);
            combine_kernel<<<(27000+255)/256, 256>>>(ocb, nullptr, odb,
                bcp[3], bdp[3], nullptr, nxt, 3);
        }
        float* t = cur; cur = nxt; nxt = t;
    }
    final_kernel<<<(NF*3+255)/256, 256>>>(cur, p1, p0, dout);
}

// round 9
// speedup vs baseline: 1.0964x; 1.0964x over previous
#include <cuda_runtime.h>
#include <math.h>
#include <stdint.h>

#define NF 3000
#define NB 1500
#define RAD2 9.0f
#define INV_R (1.0f/3.0f)
#define CAP 256
#define EPSF 1e-8f
#define FOUR_OVER_PI 1.2732395447351628f

// ---------------- static device scratch ----------------
__device__ float g_p1[NF*3];
__device__ float g_feat0[NF*9];
__device__ int   g_fcnt[NF];
__device__ int   g_fidx[NF*64];
__device__ int   g_fbase[NF*64];
__device__ float g_fw8[NF*512];
__device__ int   g_bcnt[NF];
__device__ int   g_bidx[NF*64];
__device__ int   g_bbase[NF*64];
__device__ float g_bw8[NF*512];
__device__ float g_A0[9000*192];
__device__ float g_A[(size_t)9000*6144];
__device__ float g_Abox[NF*64];
__device__ float g_cf[9000*32];
__device__ float g_co[NF*32];
__device__ float g_oc[4*9000*64];
__device__ float g_od[9000*64];
__device__ float g_out1[9000*96];
__device__ float g_out2[9000*96];

// ---------------- packed f32x2 helpers ----------------
#define PACKF2(d, lo, hi)  asm("mov.b64 %0, {%1,%2};" : "=l"(d) : "f"(lo), "f"(hi))
#define FMAF2(acc, a, b)   asm("fma.rn.f32x2 %0, %1, %2, %0;" : "+l"(acc) : "l"(a), "l"(b))
#define UNPACKF2(lo, hi, v) asm("mov.b64 {%0,%1}, %2;" : "=f"(lo), "=f"(hi) : "l"(v))

// ---------------- geometry ----------------
__device__ __forceinline__ float sgnf(float v){ return (v>0.f)?1.f:((v<0.f)?-1.f:0.f); }

__device__ __forceinline__ void ball_to_cube(float x,float y,float z,float&obx,float&oby,float&obz){
    float sq = x*x+y*y+z*z;
    float norm = sqrtf(fmaxf(sq,EPSF));
    float xy_sq = x*x+y*y;
    bool polar = (1.25f*z*z) > xy_sq;
    float s_p = sqrtf(3.0f*norm/(norm+fabsf(z)+EPSF));
    float s_e = norm / sqrtf(fmaxf(xy_sq,EPSF));
    float cx = polar ? x*s_p : x*s_e;
    float cy = polar ? y*s_p : y*s_e;
    float cz = polar ? sgnf(z)*norm : 1.5f*z;
    float nxy = sqrtf(fmaxf(cx*cx+cy*cy,EPSF));
    bool xdom = fabsf(cy) <= fabsf(cx);
    float sx = (fabsf(cx) > EPSF) ? cx : 1.0f;
    float sy = (fabsf(cy) > EPSF) ? cy : 1.0f;
    float bx1 = sgnf(cx)*nxy;
    float by1 = bx1*FOUR_OVER_PI*atanf(cy/sx);
    float by2 = sgnf(cy)*nxy;
    float bx2 = by2*FOUR_OVER_PI*atanf(cx/sy);
    float bx = xdom ? bx1 : bx2;
    float by = xdom ? by1 : by2;
    if (cx*cx+cy*cy < EPSF){ bx=0.f; by=0.f; }
    if (sq < EPSF){ bx=0.f; by=0.f; cz=0.f; }
    obx=bx; oby=by; obz=cz;
}

// ---------------- prep ----------------
__global__ void prep_kernel(const float* __restrict__ p0,const float* __restrict__ v0,
                            const float* __restrict__ a,const float* __restrict__ other,
                            const float* __restrict__ v0e,
                            float* __restrict__ p1,float* __restrict__ feat0,
                            float* __restrict__ outState){
    int i = blockIdx.x*blockDim.x + threadIdx.x;
    if (i >= NF) return;
#pragma unroll
    for (int d=0; d<3; d++){
        float vv0 = v0[i*3+d];
        float v1  = vv0 + 0.1f*a[i*3+d];
        float pp1 = p0[i*3+d] + 0.1f*(vv0+v1)*0.5f;
        p1[i*3+d]        = pp1;
        feat0[i*9+d]     = v1;
        feat0[i*9+3+d]   = other[i*3+d];
        feat0[i*9+6+d]   = v0e[i*3+d];
        outState[i*3+d]  = v0e[i*3+d];
    }
}

// ---------------- neighbor search (256 thr): exact top-64, then base-sorted ----------------
__global__ void neigh_kernel(const float* __restrict__ pin, int Mp,
                             const float* __restrict__ pout,
                             const float* __restrict__ mask, int selfEx,
                             int* __restrict__ cntO, int* __restrict__ idxO,
                             int* __restrict__ baseO, float* __restrict__ w8O){
    __shared__ float cd2[CAP];
    __shared__ int   cid[CAP];
    __shared__ unsigned long long keys[CAP];
    __shared__ int scnt;
    __shared__ int   sM[64];
    __shared__ int   sB[64];
    __shared__ float sW8[64*8];
    __shared__ unsigned skey[64];
    int n = blockIdx.x, tid = threadIdx.x;
    float qx = pout[n*3], qy = pout[n*3+1], qz = pout[n*3+2];
    if (tid==0) scnt = 0;
    __syncthreads();
    for (int m = tid; m < Mp; m += blockDim.x){
        if (selfEx && m==n) continue;
        if (mask && !(mask[m] > 0.f)) continue;
        float dx = pin[m*3]-qx, dy = pin[m*3+1]-qy, dz = pin[m*3+2]-qz;
        float d2 = dx*dx + dy*dy + dz*dz;
        if (d2 <= RAD2){
            int p = atomicAdd(&scnt, 1);
            if (p < CAP){ cd2[p]=d2; cid[p]=m; }
        }
    }
    __syncthreads();
    int cn = min(scnt, CAP);
    for (int t = tid; t < CAP; t += blockDim.x)
        keys[t] = (t < cn) ? ((((unsigned long long)__float_as_uint(cd2[t]))<<32) | (unsigned)cid[t])
                           : 0xFFFFFFFFFFFFFFFFull;
    __syncthreads();
    for (int k = 2; k <= CAP; k <<= 1){
        for (int j = k>>1; j > 0; j >>= 1){
            if (tid < 128){
                int i = ((tid & ~(j-1)) << 1) | (tid & (j-1));
                int ixj = i | j;
                bool asc = ((i & k) == 0);
                unsigned long long av = keys[i], bv = keys[ixj];
                if ((av > bv) == asc){ keys[i]=bv; keys[ixj]=av; }
            }
            __syncthreads();
        }
    }
    int keep = min(cn, 64);
    if (tid==0) cntO[n] = keep;
    for (int t = tid; t < keep; t += blockDim.x){
        unsigned long long key = keys[t];
        int m = (int)(key & 0xFFFFFFFFull);
        float dx = pin[m*3]-qx, dy = pin[m*3+1]-qy, dz = pin[m*3+2]-qz;
        float ux = dx*INV_R, uy = dy*INV_R, uz = dz*INV_R;
        float r2 = ux*ux + uy*uy + uz*uz;
        float t1 = 1.f - r2;
        float win = fminf(fmaxf(t1*t1*t1, 0.f), 1.f);
        float bx, by, bz;
        ball_to_cube(ux, uy, uz, bx, by, bz);
        float cxx = fminf(fmaxf((bx*0.5f+0.5f)*3.f, 0.f), 3.f);
        float cyy = fminf(fmaxf((by*0.5f+0.5f)*3.f, 0.f), 3.f);
        float czz = fminf(fmaxf((bz*0.5f+0.5f)*3.f, 0.f), 3.f);
        int c0x = min((int)floorf(cxx), 2);
        int c0y = min((int)floorf(cyy), 2);
        int c0z = min((int)floorf(czz), 2);
        float fx = cxx - (float)c0x, fy = cyy - (float)c0y, fz = czz - (float)c0z;
        sM[t] = m;
        sB[t] = (c0x*4 + c0y)*4 + c0z;
        float gx[2] = {1.f-fx, fx}, gy[2] = {1.f-fy, fy}, gz[2] = {1.f-fz, fz};
        int jj = 0;
        for (int i2=0;i2<2;i2++) for (int j2=0;j2<2;j2++) for (int l2=0;l2<2;l2++)
            sW8[t*8 + (jj++)] = gx[i2]*gy[j2]*gz[l2]*win;
    }
    for (int t = tid; t < 64; t += blockDim.x)
        skey[t] = (t < keep) ? (unsigned)((sB[t] << 6) | t) : 0xFFFFFFFFu;
    __syncthreads();
    for (int k = 2; k <= 64; k <<= 1){
        for (int j = k>>1; j > 0; j >>= 1){
            if (tid < 32){
                int i = ((tid & ~(j-1)) << 1) | (tid & (j-1));
                int ixj = i | j;
                bool asc = ((i & k) == 0);
                unsigned av = skey[i], bv = skey[ixj];
                if ((av > bv) == asc){ skey[i]=bv; skey[ixj]=av; }
            }
            __syncthreads();
        }
    }
    for (int t = tid; t < keep; t += blockDim.x){
        int s = (int)(skey[t] & 63u);
        idxO[n*64+t]  = sM[s];
        baseO[n*64+t] = sB[s];
#pragma unroll
        for (int j=0;j<8;j++) w8O[n*512 + t*8 + j] = sW8[s*8 + j];
    }
}

__constant__ int c_coff[8] = {0,1,4,5,16,17,20,21};

// ---------------- scatter layer0 fluid (F=9) ----------------
__global__ void scatter9(const float* __restrict__ feats,
                         const int* __restrict__ cnt, const int* __restrict__ nidx,
                         const int* __restrict__ nbase, const float* __restrict__ nw8,
                         float* __restrict__ A){
    __shared__ float planes[8*576];
    __shared__ float sfeat[64*9];
    __shared__ float sW[512];
    __shared__ int   sBase[64];
    __shared__ int   sIdx[64];
    int n = blockIdx.x, tid = threadIdx.x;
    int cn = cnt[n];
    for (int e = tid; e < 8*576; e += 96) planes[e] = 0.f;
    if (tid < cn){ sIdx[tid] = nidx[n*64+tid]; sBase[tid] = nbase[n*64+tid]; }
    for (int e = tid; e < cn*8; e += 96) sW[e] = nw8[n*512+e];
    __syncthreads();
    for (int e = tid; e < cn*9; e += 96){
        int k = e/9, f = e-k*9;
        sfeat[e] = feats[(size_t)sIdx[k]*9 + f];
    }
    __syncthreads();
    if (tid < 72){
        int j = tid/9, f = tid - j*9;
        int off = c_coff[j];
        float r = 0.f; int prevb = -1;
        for (int k = 0; k < cn; k++){
            int b = sBase[k];
            if (b != prevb){
                if (prevb >= 0) planes[j*576 + (prevb+off)*9 + f] += r;
                prevb = b; r = 0.f;
            }
            r += sW[k*8+j]*sfeat[k*9+f];
        }
        if (prevb >= 0) planes[j*576 + (prevb+off)*9 + f] += r;
    }
    __syncthreads();
    for (int e = tid; e < 576; e += 96){
        int l = e/9, f = e-l*9;
        int s = f/3, c = f-s*3;
        float v = 0.f;
#pragma unroll
        for (int j=0;j<8;j++) v += planes[j*576+e];
        A[(size_t)(n*3+s)*192 + l*3 + c] = v;
    }
}

// ---------------- scatter box (F=1) ----------------
__global__ void scatter1(const float* __restrict__ feats,
                         const int* __restrict__ cnt, const int* __restrict__ nidx,
                         const int* __restrict__ nbase, const float* __restrict__ nw8,
                         float* __restrict__ A){
    __shared__ float planes[8*8*64];
    __shared__ float sF[8*64];
    __shared__ float sW[8*512];
    __shared__ int   sBase[8*64];
    __shared__ int   sCn[8];
    int tid = threadIdx.x, nb = blockIdx.x;
    for (int e = tid; e < 8*8*64; e += 64) planes[e] = 0.f;
    for (int e = tid; e < 8*64; e += 64){
        int q = e>>6, k = e&63;
        int n = nb*8+q;
        if (k==0) sCn[q] = cnt[n];
        int cnq = cnt[n];
        if (k < cnq){ sBase[e] = nbase[n*64+k]; sF[e] = feats[nidx[n*64+k]]; }
    }
    for (int e = tid; e < 8*512; e += 64){
        int q = e>>9, r = e&511;
        sW[e] = nw8[(size_t)(nb*8+q)*512 + r];
    }
    __syncthreads();
    {
        int q = tid>>3, j = tid&7;
        int off = c_coff[j];
        int cnq = sCn[q];
        float r = 0.f; int prevb = -1;
        for (int k = 0; k < cnq; k++){
            int b = sBase[q*64+k];
            if (b != prevb){
                if (prevb >= 0) planes[(q*8+j)*64 + prevb+off] += r;
                prevb = b; r = 0.f;
            }
            r += sW[q*512 + k*8 + j]*sF[q*64+k];
        }
        if (prevb >= 0) planes[(q*8+j)*64 + prevb+off] += r;
    }
    __syncthreads();
    for (int e = tid; e < 512; e += 64){
        int q = e>>6, l = e&63;
        float v = 0.f;
#pragma unroll
        for (int j=0;j<8;j++) v += planes[(q*8+j)*64 + l];
        A[(size_t)(nb*8+q)*64 + l] = v;
    }
}

// ---------------- scatter (big) ----------------
__global__ void scatter_big(const float* __restrict__ feats, int F, int C, int S,
                            const int* __restrict__ cnt, const int* __restrict__ nidx,
                            const int* __restrict__ nbase, const float* __restrict__ nw8,
                            float* __restrict__ A, int reluA){
    extern __shared__ float acc[];
    __shared__ int sIdx[64]; __shared__ int sBase[64]; __shared__ float sW[512];
    float4* acc4 = (float4*)acc;
    int n = blockIdx.x, tid = threadIdx.x, bd = blockDim.x;
    int F4 = F >> 2;
    int cn = cnt[n];
    for (int e = tid; e < 64*F4; e += bd) acc4[e] = make_float4(0.f,0.f,0.f,0.f);
    for (int e = tid; e < cn; e += bd){ sIdx[e] = nidx[n*64+e]; sBase[e] = nbase[n*64+e]; }
    for (int e = tid; e < cn*8; e += bd) sW[e] = nw8[n*512+e];
    __syncthreads();
    int f4 = tid;
    if (f4 < F4){
        float4 r[8];
        int prevb = -1;
        for (int k = 0; k < cn; k++){
            int b = sBase[k];
            if (b != prevb){
                if (prevb >= 0){
#pragma unroll
                    for (int j=0;j<8;j++){
                        int ai = (prevb + c_coff[j])*F4 + f4;
                        float4 t = acc4[ai];
                        t.x += r[j].x; t.y += r[j].y; t.z += r[j].z; t.w += r[j].w;
                        acc4[ai] = t;
                    }
                }
                prevb = b;
#pragma unroll
                for (int j=0;j<8;j++) r[j] = make_float4(0.f,0.f,0.f,0.f);
            }
            float4 fv = ((const float4*)(feats + (size_t)sIdx[k]*F))[f4];
            if (reluA){
                fv.x = fmaxf(fv.x,0.f); fv.y = fmaxf(fv.y,0.f);
                fv.z = fmaxf(fv.z,0.f); fv.w = fmaxf(fv.w,0.f);
            }
#pragma unroll
            for (int j=0;j<8;j++){
                float w = sW[k*8+j];
                r[j].x += w*fv.x; r[j].y += w*fv.y; r[j].z += w*fv.z; r[j].w += w*fv.w;
            }
        }
        if (prevb >= 0){
#pragma unroll
            for (int j=0;j<8;j++){
                int ai = (prevb + c_coff[j])*F4 + f4;
                float4 t = acc4[ai];
                t.x += r[j].x; t.y += r[j].y; t.z += r[j].z; t.w += r[j].w;
                acc4[ai] = t;
            }
        }
    }
    __syncthreads();
    int KC = 64*C;
    float4* A4 = (float4*)A;
    for (int e4 = tid; e4 < 64*F4; e4 += bd){
        int l = e4 / F4, fl = e4 - l*F4;
        int f = fl*4;
        int s = f / C, c = f - s*C;
        A4[(((size_t)(n*S+s))*KC + l*C + c) >> 2] = acc4[e4];
    }
}

// ---- packed-f32x2 GEMM: C[M,64]=A[M,K]@B[K,64]; 256x64 tile, 256 thr, 8x8/thread ----
__global__ __launch_bounds__(256) void gemm_x2(const float* __restrict__ A,
                                               const float* __restrict__ B,
                                               float* __restrict__ Cc,
                                               int M, int K, int reluA){
    __shared__ float As[2][16][256];
    __shared__ float Bs[2][16][64];
    int tid = threadIdx.x;
    int bm = blockIdx.x * 256;
    int kLen = K / gridDim.y;
    int kBeg = blockIdx.y * kLen;
    int T = kLen >> 4;
    float* Cout = Cc + (size_t)blockIdx.y * M * 64;
    int tm = tid >> 3, tn = tid & 7;
    int arow = min(bm + tid, M-1);
    const float* Aptr = A + (size_t)arow*K + kBeg;
    int brow = tid >> 4, bcol = (tid & 15)*4;
    const float* Bptr = B + (size_t)(kBeg + brow)*64 + bcol;

    float4 pa[4], pb;
#pragma unroll
    for (int q=0;q<4;q++) pa[q] = *(const float4*)(Aptr + q*4);
    pb = *(const float4*)(Bptr);
    if (reluA){
#pragma unroll
        for (int q=0;q<4;q++){
            pa[q].x=fmaxf(pa[q].x,0.f); pa[q].y=fmaxf(pa[q].y,0.f);
            pa[q].z=fmaxf(pa[q].z,0.f); pa[q].w=fmaxf(pa[q].w,0.f);
        }
    }
#pragma unroll
    for (int q=0;q<4;q++){
        As[0][q*4+0][tid]=pa[q].x; As[0][q*4+1][tid]=pa[q].y;
        As[0][q*4+2][tid]=pa[q].z; As[0][q*4+3][tid]=pa[q].w;
    }
    *(float4*)&Bs[0][brow][bcol] = pb;
    __syncthreads();

    unsigned long long acc[8][4] = {};
    for (int t = 0; t < T; t++){
        int cb = t & 1;
        if (t+1 < T){
#pragma unroll
            for (int q=0;q<4;q++) pa[q] = *(const float4*)(Aptr + (size_t)(t+1)*16 + q*4);
            pb = *(const float4*)(Bptr + (size_t)(t+1)*16*64);
            if (reluA){
#pragma unroll
                for (int q=0;q<4;q++){
                    pa[q].x=fmaxf(pa[q].x,0.f); pa[q].y=fmaxf(pa[q].y,0.f);
                    pa[q].z=fmaxf(pa[q].z,0.f); pa[q].w=fmaxf(pa[q].w,0.f);
                }
            }
        }
#pragma unroll
        for (int kk = 0; kk < 16; kk++){
            float4 a0 = *(const float4*)&As[cb][kk][tm*8];
            float4 a1 = *(const float4*)&As[cb][kk][tm*8+4];
            ulonglong2 b01 = *(const ulonglong2*)&Bs[cb][kk][tn*8];
            ulonglong2 b23 = *(const ulonglong2*)&Bs[cb][kk][tn*8+4];
            unsigned long long bp0 = b01.x, bp1 = b01.y, bp2 = b23.x, bp3 = b23.y;
            float av[8] = {a0.x,a0.y,a0.z,a0.w,a1.x,a1.y,a1.z,a1.w};
#pragma unroll
            for (int i=0;i<8;i++){
                unsigned long long ad;
                PACKF2(ad, av[i], av[i]);
                FMAF2(acc[i][0], ad, bp0);
                FMAF2(acc[i][1], ad, bp1);
                FMAF2(acc[i][2], ad, bp2);
                FMAF2(acc[i][3], ad, bp3);
            }
        }
        if (t+1 < T){
            int nb2 = cb ^ 1;
#pragma unroll
            for (int q=0;q<4;q++){
                As[nb2][q*4+0][tid]=pa[q].x; As[nb2][q*4+1][tid]=pa[q].y;
                As[nb2][q*4+2][tid]=pa[q].z; As[nb2][q*4+3][tid]=pa[q].w;
            }
            *(float4*)&Bs[nb2][brow][bcol] = pb;
            __syncthreads();
        }
    }
#pragma unroll
    for (int i=0;i<8;i++){
        int r = bm + tm*8 + i;
        if (r >= M) continue;
#pragma unroll
        for (int jp=0;jp<4;jp++){
            float lo, hi;
            UNPACKF2(lo, hi, acc[i][jp]);
            *(float2*)&Cout[(size_t)r*64 + tn*8 + jp*2] = make_float2(lo, hi);
        }
    }
}

// ---------------- fp32 GEMM N=32 (layer 0) ----------------
__global__ void gemm32(const float* __restrict__ A, const float* __restrict__ B,
                       float* __restrict__ Cc, int M, int N, int K){
    __shared__ float As[16][64];
    __shared__ float Bs[16][64];
    int tid = threadIdx.x;
    int bm = blockIdx.x * 64;
    int tm = tid >> 4, tn = tid & 15;
    float accv[4][4] = {};
    int arow = bm + (tid >> 2);
    int akq  = (tid & 3) * 4;
    int brow = tid >> 4;
    int bcol = (tid & 15) * 4;
    for (int k0 = 0; k0 < K; k0 += 16){
        float4 a4 = make_float4(0.f,0.f,0.f,0.f);
        if (arow < M) a4 = *(const float4*)(A + (size_t)arow*K + k0 + akq);
        float4 b4 = make_float4(0.f,0.f,0.f,0.f);
        if (bcol < N) b4 = *(const float4*)(B + (size_t)(k0+brow)*N + bcol);
        __syncthreads();
        int lr = tid >> 2;
        As[akq+0][lr] = a4.x; As[akq+1][lr] = a4.y; As[akq+2][lr] = a4.z; As[akq+3][lr] = a4.w;
        *(float4*)&Bs[brow][bcol] = b4;
        __syncthreads();
#pragma unroll
        for (int kk = 0; kk < 16; kk++){
            float4 av = *(const float4*)&As[kk][tm*4];
            float4 bv = *(const float4*)&Bs[kk][tn*4];
            float ar[4] = {av.x, av.y, av.z, av.w};
            float brr[4] = {bv.x, bv.y, bv.z, bv.w};
#pragma unroll
            for (int i=0;i<4;i++)
#pragma unroll
                for (int j=0;j<4;j++) accv[i][j] += ar[i]*brr[j];
        }
    }
#pragma unroll
    for (int i=0;i<4;i++){
        int r = bm + tm*4 + i;
        if (r >= M) continue;
#pragma unroll
        for (int j=0;j<4;j++){
            int c = tn*4 + j;
            if (c < N) Cc[(size_t)r*N + c] = accv[i][j];
        }
    }
}

// ---------------- dot kernel (fp32, N<=3) ----------------
__global__ void dotn_kernel(const float* __restrict__ A, const float* __restrict__ B,
                            float* __restrict__ Cc, int M, int N, int K, int reluA){
    extern __shared__ float sBv[];
    int tid = threadIdx.x;
    for (int i = tid; i < K*N; i += blockDim.x) sBv[i] = B[i];
    __syncthreads();
    int w = tid >> 5, lane = tid & 31;
    int r = blockIdx.x * 8 + w;
    if (r >= M) return;
    float a0=0.f, a1=0.f, a2=0.f;
    const float* ap = A + (size_t)r*K;
    for (int k = lane; k < K; k += 32){
        float av = ap[k];
        if (reluA) av = fmaxf(av, 0.f);
        a0 += av * sBv[k*N+0];
        if (N > 1) a1 += av * sBv[k*N+1];
        if (N > 2) a2 += av * sBv[k*N+2];
    }
    for (int off=16; off; off>>=1){
        a0 += __shfl_down_sync(0xffffffffu, a0, off);
        a1 += __shfl_down_sync(0xffffffffu, a1, off);
        a2 += __shfl_down_sync(0xffffffffu, a2, off);
    }
    if (lane == 0){
        Cc[(size_t)r*N+0] = a0;
        if (N > 1) Cc[(size_t)r*N+1] = a1;
        if (N > 2) Cc[(size_t)r*N+2] = a2;
    }
}

// ---------------- elementwise ----------------
__global__ void combine0_kernel(const float* __restrict__ co, const float* __restrict__ cf,
                                const float* __restrict__ feat0,
                                const float* __restrict__ b0o, const float* __restrict__ b0f,
                                const float* __restrict__ wdf, const float* __restrict__ bdf,
                                float* __restrict__ out){
    int e = blockIdx.x*blockDim.x + threadIdx.x;
    if (e >= 9000*96) return;
    int row = e / 96, o = e - row*96;
    int n = row / 3;
    float v;
    if (o < 32) v = co[n*32+o] + b0o[o];
    else if (o < 64) v = cf[(size_t)row*32 + (o-32)] + b0f[o-32];
    else {
        int oo = o - 64;
        v = bdf[oo];
        for (int c=0;c<3;c++) v += feat0[row*3+c]*wdf[c*32+oo];
    }
    out[e] = v;
}

__global__ void combine_kernel(const float* __restrict__ oc, int nsplit,
                               const float* __restrict__ od,
                               const float* __restrict__ bc, const float* __restrict__ bd,
                               const float* __restrict__ prev, float* __restrict__ out, int C){
    int e = blockIdx.x*blockDim.x + threadIdx.x;
    if (e >= 9000*C) return;
    int o = e % C;
    float v = bc[o] + od[e] + bd[o];
    for (int j = 0; j < nsplit; j++) v += oc[(size_t)j*9000*64 + e];
    if (prev) v += prev[e];
    out[e] = v;
}

__global__ void final_kernel(const float* __restrict__ out4, const float* __restrict__ p1,
                             const float* __restrict__ p0, float* __restrict__ dout){
    int e = blockIdx.x*blockDim.x + threadIdx.x;
    if (e >= NF*3) return;
    int n = e/3, d = e - n*3;
    float pc0 = out4[(n*3+0)*3+d] * 0.25f * (1.0f/16.0f);
    float pc1 = out4[(n*3+1)*3+d] * 0.25f;
    float pc2 = out4[(n*3+2)*3+d] * 0.25f;
    float p_c = p1[e] + pc0;
    dout[e] = p_c;
    dout[9000 + e] = (p_c - p0[e]) / 0.1f;
    dout[18000 + n*6 + d]     = pc1;
    dout[18000 + n*6 + 3 + d] = pc2;
}

// ---------------- launch ----------------
extern "C" void kernel_launch(void* const* d_in, const int* in_sizes, int n_in,
                              void* d_out, int out_size){
    const float* v0e  = (const float*)d_in[1];
    const float* p0   = (const float*)d_in[2];
    const float* v0   = (const float*)d_in[3];
    const float* a    = (const float*)d_in[4];
    const float* other= (const float*)d_in[5];
    const float* box  = (const float*)d_in[6];
    const float* boxf = (const float*)d_in[7];
    const float* bmask= (const float*)d_in[9];
    const float* k0f  = (const float*)d_in[10];
    const float* b0f  = (const float*)d_in[11];
    const float* k0o  = (const float*)d_in[12];
    const float* b0o  = (const float*)d_in[13];
    const float* wdf  = (const float*)d_in[14];
    const float* bdf  = (const float*)d_in[15];
    const float *kc[4], *bcp[4], *wd[4], *bdp[4];
    if (in_sizes[18] == 262144){
        for (int i=0;i<4;i++){
            kc[i]=(const float*)d_in[16+2*i]; bcp[i]=(const float*)d_in[17+2*i];
            wd[i]=(const float*)d_in[24+2*i]; bdp[i]=(const float*)d_in[25+2*i];
        }
    } else {
        for (int i=0;i<4;i++){
            kc[i]=(const float*)d_in[16+4*i]; bcp[i]=(const float*)d_in[17+4*i];
            wd[i]=(const float*)d_in[18+4*i]; bdp[i]=(const float*)d_in[19+4*i];
        }
    }
    float* dout = (float*)d_out;

    float *p1, *feat0, *A0, *A, *Abox, *cfb, *cob, *ocb, *odb, *o1, *o2, *fw8, *bw8;
    int *fcnt, *fidx, *fbase, *bcnt, *bidx, *bbase;
    cudaGetSymbolAddress((void**)&p1, g_p1);
    cudaGetSymbolAddress((void**)&feat0, g_feat0);
    cudaGetSymbolAddress((void**)&A0, g_A0);
    cudaGetSymbolAddress((void**)&A, g_A);
    cudaGetSymbolAddress((void**)&Abox, g_Abox);
    cudaGetSymbolAddress((void**)&cfb, g_cf);
    cudaGetSymbolAddress((void**)&cob, g_co);
    cudaGetSymbolAddress((void**)&ocb, g_oc);
    cudaGetSymbolAddress((void**)&odb, g_od);
    cudaGetSymbolAddress((void**)&o1, g_out1);
    cudaGetSymbolAddress((void**)&o2, g_out2);
    cudaGetSymbolAddress((void**)&fw8, g_fw8);
    cudaGetSymbolAddress((void**)&bw8, g_bw8);
    cudaGetSymbolAddress((void**)&fcnt, g_fcnt);
    cudaGetSymbolAddress((void**)&fidx, g_fidx);
    cudaGetSymbolAddress((void**)&fbase, g_fbase);
    cudaGetSymbolAddress((void**)&bcnt, g_bcnt);
    cudaGetSymbolAddress((void**)&bidx, g_bidx);
    cudaGetSymbolAddress((void**)&bbase, g_bbase);

    cudaFuncSetAttribute(scatter_big, cudaFuncAttributeMaxDynamicSharedMemorySize, 80000);
    cudaFuncSetAttribute(dotn_kernel, cudaFuncAttributeMaxDynamicSharedMemorySize, 50000);

    prep_kernel<<<(NF+127)/128, 128>>>(p0, v0, a, other, v0e, p1, feat0, dout + 36000);
    neigh_kernel<<<NF, 256>>>(p1, NF, p1, nullptr, 1, fcnt, fidx, fbase, fw8);
    neigh_kernel<<<NF, 256>>>(box, NB, p1, bmask, 0, bcnt, bidx, bbase, bw8);

    // layer 0
    scatter9<<<NF, 96>>>(feat0, fcnt, fidx, fbase, fw8, A0);
    gemm32<<<(9000+63)/64, 256>>>(A0, k0f, cfb, 9000, 32, 192);
    scatter1<<<NF/8, 64>>>(boxf, bcnt, bidx, bbase, bw8, Abox);
    gemm32<<<(3000+63)/64, 256>>>(Abox, k0o, cob, 3000, 32, 64);
    combine0_kernel<<<(9000*96+255)/256, 256>>>(cob, cfb, feat0, b0o, b0f, wdf, bdf, o1);

    int Cin[4] = {96, 64, 64, 64};
    float* cur = o1; float* nxt = o2;
    for (int i=0;i<4;i++){
        int ci = Cin[i];
        int F = 3*ci, F4 = F/4;
        int K = 64*ci;
        int bD = ((F4 + 31)/32)*32;
        scatter_big<<<NF, bD, (size_t)64*F*4>>>(cur, F, ci, 3, fcnt, fidx, fbase, fw8, A, 1);
        if (i < 3){
            gemm_x2<<<dim3(36,4), 256>>>(A,  kc[i], ocb, 9000, K, 0);
            gemm_x2<<<dim3(36,1), 256>>>(cur, wd[i], odb, 9000, ci, 1);
            combine_kernel<<<(9000*64+255)/256, 256>>>(ocb, 4, odb,
                bcp[i], bdp[i], (i==1||i==2) ? cur : nullptr, nxt, 64);
        } else {
            dotn_kernel<<<(9000+7)/8, 256, (size_t)K*3*4>>>(A,  kc[3], ocb, 9000, 3, K, 0);
            dotn_kernel<<<(9000+7)/8, 256, (size_t)ci*3*4>>>(cur, wd[3], odb, 9000, 3, ci, 1);
            combine_kernel<<<(27000+255)/256, 256>>>(ocb, 1, odb,
                bcp[3], bdp[3], nullptr, nxt, 3);
        }
        float* t = cur; cur = nxt; nxt = t;
    }
    final_kernel<<<(NF*3+255)/256, 256>>>(cur, p1, p0, dout);
}

// round 10
// speedup vs baseline: 1.2784x; 1.1661x over previous
#include <cuda_runtime.h>
#include <cuda_bf16.h>
#include <math.h>
#include <stdint.h>

#define NF 3000
#define NB 1500
#define RAD2 9.0f
#define INV_R (1.0f/3.0f)
#define CAP 256
#define EPSF 1e-8f
#define FOUR_OVER_PI 1.2732395447351628f

// ---------------- static device scratch ----------------
__device__ float g_p1[NF*3];
__device__ float g_feat0[NF*9];
__device__ int   g_fcnt[NF];
__device__ int   g_fidx[NF*64];
__device__ int   g_fbase[NF*64];
__device__ float g_fw8[NF*512];
__device__ int   g_bcnt[NF];
__device__ int   g_bidx[NF*64];
__device__ int   g_bbase[NF*64];
__device__ float g_bw8[NF*512];
__device__ float g_A0[9000*192];
__device__ float g_Abox[NF*64];
__device__ __nv_bfloat16 g_Ah[(size_t)9088*6144];
__device__ __nv_bfloat16 g_Al[(size_t)9088*6144];
__device__ __nv_bfloat16 g_Bh[64*6144];
__device__ __nv_bfloat16 g_Bl[64*6144];
__device__ float g_cf[9000*32];
__device__ float g_co[NF*32];
__device__ float g_oc[2*9000*64];
__device__ float g_od[9000*64];
__device__ float g_out1[9000*96];
__device__ float g_out2[9000*96];

// ---------------- helpers ----------------
__device__ __forceinline__ uint32_t smem_u32(const void* p){
    uint32_t a;
    asm("{ .reg .u64 t; cvta.to.shared.u64 t, %1; cvt.u32.u64 %0, t; }" : "=r"(a) : "l"(p));
    return a;
}
__device__ __forceinline__ void ldsm_x4(uint32_t& r0, uint32_t& r1, uint32_t& r2, uint32_t& r3, uint32_t addr){
    asm volatile("ldmatrix.sync.aligned.m8n8.x4.shared.b16 {%0,%1,%2,%3}, [%4];"
        : "=r"(r0), "=r"(r1), "=r"(r2), "=r"(r3) : "r"(addr));
}
__device__ __forceinline__ void ldsm_x2(uint32_t& r0, uint32_t& r1, uint32_t addr){
    asm volatile("ldmatrix.sync.aligned.m8n8.x2.shared.b16 {%0,%1}, [%2];"
        : "=r"(r0), "=r"(r1) : "r"(addr));
}
__device__ __forceinline__ void mma_bf16(float* c, const uint32_t* a, const uint32_t* b){
    asm volatile("mma.sync.aligned.m16n8k16.row.col.f32.bf16.bf16.f32 "
        "{%0,%1,%2,%3}, {%4,%5,%6,%7}, {%8,%9}, {%0,%1,%2,%3};"
        : "+f"(c[0]), "+f"(c[1]), "+f"(c[2]), "+f"(c[3])
        : "r"(a[0]), "r"(a[1]), "r"(a[2]), "r"(a[3]), "r"(b[0]), "r"(b[1]));
}

// ---------------- geometry ----------------
__device__ __forceinline__ float sgnf(float v){ return (v>0.f)?1.f:((v<0.f)?-1.f:0.f); }

__device__ __forceinline__ void ball_to_cube(float x,float y,float z,float&obx,float&oby,float&obz){
    float sq = x*x+y*y+z*z;
    float norm = sqrtf(fmaxf(sq,EPSF));
    float xy_sq = x*x+y*y;
    bool polar = (1.25f*z*z) > xy_sq;
    float s_p = sqrtf(3.0f*norm/(norm+fabsf(z)+EPSF));
    float s_e = norm / sqrtf(fmaxf(xy_sq,EPSF));
    float cx = polar ? x*s_p : x*s_e;
    float cy = polar ? y*s_p : y*s_e;
    float cz = polar ? sgnf(z)*norm : 1.5f*z;
    float nxy = sqrtf(fmaxf(cx*cx+cy*cy,EPSF));
    bool xdom = fabsf(cy) <= fabsf(cx);
    float sx = (fabsf(cx) > EPSF) ? cx : 1.0f;
    float sy = (fabsf(cy) > EPSF) ? cy : 1.0f;
    float bx1 = sgnf(cx)*nxy;
    float by1 = bx1*FOUR_OVER_PI*atanf(cy/sx);
    float by2 = sgnf(cy)*nxy;
    float bx2 = by2*FOUR_OVER_PI*atanf(cx/sy);
    float bx = xdom ? bx1 : bx2;
    float by = xdom ? by1 : by2;
    if (cx*cx+cy*cy < EPSF){ bx=0.f; by=0.f; }
    if (sq < EPSF){ bx=0.f; by=0.f; cz=0.f; }
    obx=bx; oby=by; obz=cz;
}

// ---------------- prep ----------------
__global__ void prep_kernel(const float* __restrict__ p0,const float* __restrict__ v0,
                            const float* __restrict__ a,const float* __restrict__ other,
                            const float* __restrict__ v0e,
                            float* __restrict__ p1,float* __restrict__ feat0,
                            float* __restrict__ outState){
    int i = blockIdx.x*blockDim.x + threadIdx.x;
    if (i >= NF) return;
#pragma unroll
    for (int d=0; d<3; d++){
        float vv0 = v0[i*3+d];
        float v1  = vv0 + 0.1f*a[i*3+d];
        float pp1 = p0[i*3+d] + 0.1f*(vv0+v1)*0.5f;
        p1[i*3+d]        = pp1;
        feat0[i*9+d]     = v1;
        feat0[i*9+3+d]   = other[i*3+d];
        feat0[i*9+6+d]   = v0e[i*3+d];
        outState[i*3+d]  = v0e[i*3+d];
    }
}

// ---------------- neighbor search ----------------
__global__ void neigh_kernel(const float* __restrict__ pin, int Mp,
                             const float* __restrict__ pout,
                             const float* __restrict__ mask, int selfEx,
                             int* __restrict__ cntO, int* __restrict__ idxO,
                             int* __restrict__ baseO, float* __restrict__ w8O){
    __shared__ float cd2[CAP];
    __shared__ int   cid[CAP];
    __shared__ unsigned long long keys[CAP];
    __shared__ int scnt;
    __shared__ int   sM[64];
    __shared__ int   sB[64];
    __shared__ float sW8[64*8];
    __shared__ unsigned skey[64];
    int n = blockIdx.x, tid = threadIdx.x;
    float qx = pout[n*3], qy = pout[n*3+1], qz = pout[n*3+2];
    if (tid==0) scnt = 0;
    __syncthreads();
    for (int m = tid; m < Mp; m += blockDim.x){
        if (selfEx && m==n) continue;
        if (mask && !(mask[m] > 0.f)) continue;
        float dx = pin[m*3]-qx, dy = pin[m*3+1]-qy, dz = pin[m*3+2]-qz;
        float d2 = dx*dx + dy*dy + dz*dz;
        if (d2 <= RAD2){
            int p = atomicAdd(&scnt, 1);
            if (p < CAP){ cd2[p]=d2; cid[p]=m; }
        }
    }
    __syncthreads();
    int cn = min(scnt, CAP);
    for (int t = tid; t < CAP; t += blockDim.x)
        keys[t] = (t < cn) ? ((((unsigned long long)__float_as_uint(cd2[t]))<<32) | (unsigned)cid[t])
                           : 0xFFFFFFFFFFFFFFFFull;
    __syncthreads();
    for (int k = 2; k <= CAP; k <<= 1){
        for (int j = k>>1; j > 0; j >>= 1){
            if (tid < 128){
                int i = ((tid & ~(j-1)) << 1) | (tid & (j-1));
                int ixj = i | j;
                bool asc = ((i & k) == 0);
                unsigned long long av = keys[i], bv = keys[ixj];
                if ((av > bv) == asc){ keys[i]=bv; keys[ixj]=av; }
            }
            __syncthreads();
        }
    }
    int keep = min(cn, 64);
    if (tid==0) cntO[n] = keep;
    for (int t = tid; t < keep; t += blockDim.x){
        unsigned long long key = keys[t];
        int m = (int)(key & 0xFFFFFFFFull);
        float dx = pin[m*3]-qx, dy = pin[m*3+1]-qy, dz = pin[m*3+2]-qz;
        float ux = dx*INV_R, uy = dy*INV_R, uz = dz*INV_R;
        float r2 = ux*ux + uy*uy + uz*uz;
        float t1 = 1.f - r2;
        float win = fminf(fmaxf(t1*t1*t1, 0.f), 1.f);
        float bx, by, bz;
        ball_to_cube(ux, uy, uz, bx, by, bz);
        float cxx = fminf(fmaxf((bx*0.5f+0.5f)*3.f, 0.f), 3.f);
        float cyy = fminf(fmaxf((by*0.5f+0.5f)*3.f, 0.f), 3.f);
        float czz = fminf(fmaxf((bz*0.5f+0.5f)*3.f, 0.f), 3.f);
        int c0x = min((int)floorf(cxx), 2);
        int c0y = min((int)floorf(cyy), 2);
        int c0z = min((int)floorf(czz), 2);
        float fx = cxx - (float)c0x, fy = cyy - (float)c0y, fz = czz - (float)c0z;
        sM[t] = m;
        sB[t] = (c0x*4 + c0y)*4 + c0z;
        float gx[2] = {1.f-fx, fx}, gy[2] = {1.f-fy, fy}, gz[2] = {1.f-fz, fz};
        int jj = 0;
        for (int i2=0;i2<2;i2++) for (int j2=0;j2<2;j2++) for (int l2=0;l2<2;l2++)
            sW8[t*8 + (jj++)] = gx[i2]*gy[j2]*gz[l2]*win;
    }
    for (int t = tid; t < 64; t += blockDim.x)
        skey[t] = (t < keep) ? (unsigned)((sB[t] << 6) | t) : 0xFFFFFFFFu;
    __syncthreads();
    for (int k = 2; k <= 64; k <<= 1){
        for (int j = k>>1; j > 0; j >>= 1){
            if (tid < 32){
                int i = ((tid & ~(j-1)) << 1) | (tid & (j-1));
                int ixj = i | j;
                bool asc = ((i & k) == 0);
                unsigned av = skey[i], bv = skey[ixj];
                if ((av > bv) == asc){ skey[i]=bv; skey[ixj]=av; }
            }
            __syncthreads();
        }
    }
    for (int t = tid; t < keep; t += blockDim.x){
        int s = (int)(skey[t] & 63u);
        idxO[n*64+t]  = sM[s];
        baseO[n*64+t] = sB[s];
#pragma unroll
        for (int j=0;j<8;j++) w8O[n*512 + t*8 + j] = sW8[s*8 + j];
    }
}

__constant__ int c_coff[8] = {0,1,4,5,16,17,20,21};

// ---------------- scatter layer0 fluid (F=9) ----------------
__global__ void scatter9(const float* __restrict__ feats,
                         const int* __restrict__ cnt, const int* __restrict__ nidx,
                         const int* __restrict__ nbase, const float* __restrict__ nw8,
                         float* __restrict__ A){
    __shared__ float planes[8*576];
    __shared__ float sfeat[64*9];
    __shared__ float sW[512];
    __shared__ int   sBase[64];
    __shared__ int   sIdx[64];
    int n = blockIdx.x, tid = threadIdx.x;
    int cn = cnt[n];
    for (int e = tid; e < 8*576; e += 96) planes[e] = 0.f;
    if (tid < cn){ sIdx[tid] = nidx[n*64+tid]; sBase[tid] = nbase[n*64+tid]; }
    for (int e = tid; e < cn*8; e += 96) sW[e] = nw8[n*512+e];
    __syncthreads();
    for (int e = tid; e < cn*9; e += 96){
        int k = e/9, f = e-k*9;
        sfeat[e] = feats[(size_t)sIdx[k]*9 + f];
    }
    __syncthreads();
    if (tid < 72){
        int j = tid/9, f = tid - j*9;
        int off = c_coff[j];
        float r = 0.f; int prevb = -1;
        for (int k = 0; k < cn; k++){
            int b = sBase[k];
            if (b != prevb){
                if (prevb >= 0) planes[j*576 + (prevb+off)*9 + f] += r;
                prevb = b; r = 0.f;
            }
            r += sW[k*8+j]*sfeat[k*9+f];
        }
        if (prevb >= 0) planes[j*576 + (prevb+off)*9 + f] += r;
    }
    __syncthreads();
    for (int e = tid; e < 576; e += 96){
        int l = e/9, f = e-l*9;
        int s = f/3, c = f-s*3;
        float v = 0.f;
#pragma unroll
        for (int j=0;j<8;j++) v += planes[j*576+e];
        A[(size_t)(n*3+s)*192 + l*3 + c] = v;
    }
}

// ---------------- scatter box (F=1) ----------------
__global__ void scatter1(const float* __restrict__ feats,
                         const int* __restrict__ cnt, const int* __restrict__ nidx,
                         const int* __restrict__ nbase, const float* __restrict__ nw8,
                         float* __restrict__ A){
    __shared__ float planes[8*8*64];
    __shared__ float sF[8*64];
    __shared__ float sW[8*512];
    __shared__ int   sBase[8*64];
    __shared__ int   sCn[8];
    int tid = threadIdx.x, nb = blockIdx.x;
    for (int e = tid; e < 8*8*64; e += 64) planes[e] = 0.f;
    for (int e = tid; e < 8*64; e += 64){
        int q = e>>6, k = e&63;
        int n = nb*8+q;
        if (k==0) sCn[q] = cnt[n];
        int cnq = cnt[n];
        if (k < cnq){ sBase[e] = nbase[n*64+k]; sF[e] = feats[nidx[n*64+k]]; }
    }
    for (int e = tid; e < 8*512; e += 64){
        int q = e>>9, r = e&511;
        sW[e] = nw8[(size_t)(nb*8+q)*512 + r];
    }
    __syncthreads();
    {
        int q = tid>>3, j = tid&7;
        int off = c_coff[j];
        int cnq = sCn[q];
        float r = 0.f; int prevb = -1;
        for (int k = 0; k < cnq; k++){
            int b = sBase[q*64+k];
            if (b != prevb){
                if (prevb >= 0) planes[(q*8+j)*64 + prevb+off] += r;
                prevb = b; r = 0.f;
            }
            r += sW[q*512 + k*8 + j]*sF[q*64+k];
        }
        if (prevb >= 0) planes[(q*8+j)*64 + prevb+off] += r;
    }
    __syncthreads();
    for (int e = tid; e < 512; e += 64){
        int q = e>>6, l = e&63;
        float v = 0.f;
#pragma unroll
        for (int j=0;j<8;j++) v += planes[(q*8+j)*64 + l];
        A[(size_t)(nb*8+q)*64 + l] = v;
    }
}

// ---------------- scatter (big): emits bf16 hi/lo A (relu applied to feats) ----------------
__global__ void scatter_big(const float* __restrict__ feats, int F, int C,
                            const int* __restrict__ cnt, const int* __restrict__ nidx,
                            const int* __restrict__ nbase, const float* __restrict__ nw8,
                            __nv_bfloat16* __restrict__ Ah, __nv_bfloat16* __restrict__ Al,
                            int K){
    extern __shared__ float acc[];
    __shared__ int sIdx[64]; __shared__ int sBase[64]; __shared__ float sW[512];
    float4* acc4 = (float4*)acc;
    int n = blockIdx.x, tid = threadIdx.x, bd = blockDim.x;
    int F4 = F >> 2;
    int cn = cnt[n];
    for (int e = tid; e < 64*F4; e += bd) acc4[e] = make_float4(0.f,0.f,0.f,0.f);
    for (int e = tid; e < cn; e += bd){ sIdx[e] = nidx[n*64+e]; sBase[e] = nbase[n*64+e]; }
    for (int e = tid; e < cn*8; e += bd) sW[e] = nw8[n*512+e];
    __syncthreads();
    int f4 = tid;
    if (f4 < F4){
        float4 r[8];
        int prevb = -1;
        for (int k = 0; k < cn; k++){
            int b = sBase[k];
            if (b != prevb){
                if (prevb >= 0){
#pragma unroll
                    for (int j=0;j<8;j++){
                        int ai = (prevb + c_coff[j])*F4 + f4;
                        float4 t = acc4[ai];
                        t.x += r[j].x; t.y += r[j].y; t.z += r[j].z; t.w += r[j].w;
                        acc4[ai] = t;
                    }
                }
                prevb = b;
#pragma unroll
                for (int j=0;j<8;j++) r[j] = make_float4(0.f,0.f,0.f,0.f);
            }
            float4 fv = ((const float4*)(feats + (size_t)sIdx[k]*F))[f4];
            fv.x = fmaxf(fv.x,0.f); fv.y = fmaxf(fv.y,0.f);
            fv.z = fmaxf(fv.z,0.f); fv.w = fmaxf(fv.w,0.f);
#pragma unroll
            for (int j=0;j<8;j++){
                float w = sW[k*8+j];
                r[j].x += w*fv.x; r[j].y += w*fv.y; r[j].z += w*fv.z; r[j].w += w*fv.w;
            }
        }
        if (prevb >= 0){
#pragma unroll
            for (int j=0;j<8;j++){
                int ai = (prevb + c_coff[j])*F4 + f4;
                float4 t = acc4[ai];
                t.x += r[j].x; t.y += r[j].y; t.z += r[j].z; t.w += r[j].w;
                acc4[ai] = t;
            }
        }
    }
    __syncthreads();
    for (int e4 = tid; e4 < 64*F4; e4 += bd){
        int l = e4 / F4, fl = e4 - l*F4;
        int f = fl*4;
        int s = f / C, c = f - s*C;
        float4 v = acc4[e4];
        size_t base = (size_t)(n*3+s)*K + l*C + c;
        float vv[4] = {v.x, v.y, v.z, v.w};
        __nv_bfloat16 h[4], lo[4];
#pragma unroll
        for (int q=0;q<4;q++){
            h[q] = __float2bfloat16(vv[q]);
            lo[q] = __float2bfloat16(vv[q] - __bfloat162float(h[q]));
        }
        *(__nv_bfloat162*)(Ah+base)   = __nv_bfloat162(h[0], h[1]);
        *(__nv_bfloat162*)(Ah+base+2) = __nv_bfloat162(h[2], h[3]);
        *(__nv_bfloat162*)(Al+base)   = __nv_bfloat162(lo[0], lo[1]);
        *(__nv_bfloat162*)(Al+base+2) = __nv_bfloat162(lo[2], lo[3]);
    }
}

// ---------------- B conversion: [K,N] fp32 -> [64][K] bf16 hi/lo (n-major, zero pad) ----------------
__global__ void convB(const float* __restrict__ B, int N, int K,
                      __nv_bfloat16* __restrict__ BhT, __nv_bfloat16* __restrict__ BlT){
    int e = blockIdx.x*blockDim.x + threadIdx.x;
    if (e >= 64*K) return;
    int n = e / K, k = e - n*K;
    float v = (n < N) ? B[(size_t)k*N + n] : 0.f;
    __nv_bfloat16 h = __float2bfloat16(v);
    BhT[e] = h;
    BlT[e] = __float2bfloat16(v - __bfloat162float(h));
}

// ---------------- bf16 MMA GEMM: C[M,64] = (Ah+Al)[M,K] @ (Bh+Bl)[64,K]^T ----------------
// 128x64 CTA tile, 8 warps (warp = 32x32), KC=32 chunks double-buffered.
__global__ __launch_bounds__(256) void gemm_mma(const __nv_bfloat16* __restrict__ Ah,
                                                const __nv_bfloat16* __restrict__ Al,
                                                const __nv_bfloat16* __restrict__ Bh,
                                                const __nv_bfloat16* __restrict__ Bl,
                                                float* __restrict__ Cc, int M, int K){
    extern __shared__ __nv_bfloat16 sm[];
    const int RS = 40;              // row stride in bf16 (32 + 8 pad = 80B, conflict-free LDSM)
    const int OFF_AL = 128*RS;      // 5120
    const int OFF_BH = 2*128*RS;    // 10240
    const int OFF_BL = 2*128*RS + 64*RS;  // 12800
    const int BUFSZ  = 2*128*RS + 2*64*RS; // 15360 bf16 per buffer
    int tid = threadIdx.x;
    int bm = blockIdx.x*128;
    int kLen = K / gridDim.y;
    int kBeg = blockIdx.y*kLen;
    int T = kLen >> 5;
    float* Cout = Cc + (size_t)blockIdx.y * M * 64;

    int arow = tid >> 1, ahalf = tid & 1;              // 2 thr/row, 16 bf16 each
    const __nv_bfloat16* AhG = Ah + (size_t)(bm+arow)*K + kBeg + ahalf*16;
    const __nv_bfloat16* AlG = Al + (size_t)(bm+arow)*K + kBeg + ahalf*16;
    int brow = tid >> 2, bq = tid & 3;                 // 4 thr/row, 8 bf16 each
    const __nv_bfloat16* BhG = Bh + (size_t)brow*K + kBeg + bq*8;
    const __nv_bfloat16* BlG = Bl + (size_t)brow*K + kBeg + bq*8;

    uint32_t sbase = smem_u32(sm);
    int wid = tid >> 5, lane = tid & 31;
    int wm = wid & 3, wn = wid >> 2;

    uint4 ra0, ra1, rl0, rl1, rbh, rbl;
    // prologue: chunk 0 -> buf 0
    ra0 = *(const uint4*)(AhG);     ra1 = *(const uint4*)(AhG + 8);
    rl0 = *(const uint4*)(AlG);     rl1 = *(const uint4*)(AlG + 8);
    rbh = *(const uint4*)(BhG);     rbl = *(const uint4*)(BlG);
    {
        __nv_bfloat16* buf = sm;
        *(uint4*)(buf + arow*RS + ahalf*16)     = ra0;
        *(uint4*)(buf + arow*RS + ahalf*16 + 8) = ra1;
        *(uint4*)(buf + OFF_AL + arow*RS + ahalf*16)     = rl0;
        *(uint4*)(buf + OFF_AL + arow*RS + ahalf*16 + 8) = rl1;
        *(uint4*)(buf + OFF_BH + brow*RS + bq*8) = rbh;
        *(uint4*)(buf + OFF_BL + brow*RS + bq*8) = rbl;
    }
    __syncthreads();

    float acc[2][4][4];
#pragma unroll
    for (int mt=0;mt<2;mt++)
#pragma unroll
        for (int nt=0;nt<4;nt++)
#pragma unroll
            for (int q=0;q<4;q++) acc[mt][nt][q] = 0.f;

    for (int t = 0; t < T; t++){
        if (t+1 < T){
            ra0 = *(const uint4*)(AhG + (size_t)(t+1)*32);
            ra1 = *(const uint4*)(AhG + (size_t)(t+1)*32 + 8);
            rl0 = *(const uint4*)(AlG + (size_t)(t+1)*32);
            rl1 = *(const uint4*)(AlG + (size_t)(t+1)*32 + 8);
            rbh = *(const uint4*)(BhG + (size_t)(t+1)*32);
            rbl = *(const uint4*)(BlG + (size_t)(t+1)*32);
        }
        uint32_t bufo = (uint32_t)((t & 1) * BUFSZ) * 2;   // byte offset
#pragma unroll
        for (int ks = 0; ks < 2; ks++){
            int k0 = ks*16;
            uint32_t afh[2][4], afl[2][4];
#pragma unroll
            for (int mt=0;mt<2;mt++){
                int row = wm*32 + mt*16 + (lane & 15);
                int col = k0 + (lane >> 4)*8;
                uint32_t addr = sbase + bufo + (uint32_t)(row*RS + col)*2;
                ldsm_x4(afh[mt][0], afh[mt][1], afh[mt][2], afh[mt][3], addr);
                ldsm_x4(afl[mt][0], afl[mt][1], afl[mt][2], afl[mt][3], addr + OFF_AL*2);
            }
            uint32_t bfh[4][2], bfl[4][2];
#pragma unroll
            for (int nt=0;nt<4;nt++){
                int row = wn*32 + nt*8 + (lane & 7);
                int col = k0 + ((lane >> 3) & 1)*8;
                uint32_t addr = sbase + bufo + (uint32_t)(OFF_BH + row*RS + col)*2;
                ldsm_x2(bfh[nt][0], bfh[nt][1], addr);
                ldsm_x2(bfl[nt][0], bfl[nt][1], addr + (OFF_BL-OFF_BH)*2);
            }
#pragma unroll
            for (int mt=0;mt<2;mt++)
#pragma unroll
                for (int nt=0;nt<4;nt++){
                    mma_bf16(acc[mt][nt], afh[mt], bfh[nt]);
                    mma_bf16(acc[mt][nt], afh[mt], bfl[nt]);
                    mma_bf16(acc[mt][nt], afl[mt], bfh[nt]);
                }
        }
        if (t+1 < T){
            __nv_bfloat16* buf = sm + ((t+1) & 1) * BUFSZ;
            *(uint4*)(buf + arow*RS + ahalf*16)     = ra0;
            *(uint4*)(buf + arow*RS + ahalf*16 + 8) = ra1;
            *(uint4*)(buf + OFF_AL + arow*RS + ahalf*16)     = rl0;
            *(uint4*)(buf + OFF_AL + arow*RS + ahalf*16 + 8) = rl1;
            *(uint4*)(buf + OFF_BH + brow*RS + bq*8) = rbh;
            *(uint4*)(buf + OFF_BL + brow*RS + bq*8) = rbl;
            __syncthreads();
        }
    }
#pragma unroll
    for (int mt=0;mt<2;mt++){
#pragma unroll
        for (int nt=0;nt<4;nt++){
            int r0 = bm + wm*32 + mt*16 + (lane >> 2);
            int c0 = wn*32 + nt*8 + (lane & 3)*2;
            if (r0 < M)     *(float2*)&Cout[(size_t)r0*64 + c0]     = make_float2(acc[mt][nt][0], acc[mt][nt][1]);
            if (r0+8 < M)   *(float2*)&Cout[(size_t)(r0+8)*64 + c0] = make_float2(acc[mt][nt][2], acc[mt][nt][3]);
        }
    }
}

// ---- packed-f32x2 GEMM (dense branch, small K) ----
#define PACKF2(d, lo, hi)  asm("mov.b64 %0, {%1,%2};" : "=l"(d) : "f"(lo), "f"(hi))
#define FMAF2(acc, a, b)   asm("fma.rn.f32x2 %0, %1, %2, %0;" : "+l"(acc) : "l"(a), "l"(b))
#define UNPACKF2(lo, hi, v) asm("mov.b64 {%0,%1}, %2;" : "=f"(lo), "=f"(hi) : "l"(v))

__global__ __launch_bounds__(256) void gemm_x2(const float* __restrict__ A,
                                               const float* __restrict__ B,
                                               float* __restrict__ Cc,
                                               int M, int K, int reluA){
    __shared__ float As[2][16][256];
    __shared__ float Bs[2][16][64];
    int tid = threadIdx.x;
    int bm = blockIdx.x * 256;
    int T = K >> 4;
    int tm = tid >> 3, tn = tid & 7;
    int arow = min(bm + tid, M-1);
    const float* Aptr = A + (size_t)arow*K;
    int brow = tid >> 4, bcol = (tid & 15)*4;
    const float* Bptr = B + (size_t)brow*64 + bcol;

    float4 pa[4], pb;
#pragma unroll
    for (int q=0;q<4;q++) pa[q] = *(const float4*)(Aptr + q*4);
    pb = *(const float4*)(Bptr);
    if (reluA){
#pragma unroll
        for (int q=0;q<4;q++){
            pa[q].x=fmaxf(pa[q].x,0.f); pa[q].y=fmaxf(pa[q].y,0.f);
            pa[q].z=fmaxf(pa[q].z,0.f); pa[q].w=fmaxf(pa[q].w,0.f);
        }
    }
#pragma unroll
    for (int q=0;q<4;q++){
        As[0][q*4+0][tid]=pa[q].x; As[0][q*4+1][tid]=pa[q].y;
        As[0][q*4+2][tid]=pa[q].z; As[0][q*4+3][tid]=pa[q].w;
    }
    *(float4*)&Bs[0][brow][bcol] = pb;
    __syncthreads();

    unsigned long long acc[8][4] = {};
    for (int t = 0; t < T; t++){
        int cb = t & 1;
        if (t+1 < T){
#pragma unroll
            for (int q=0;q<4;q++) pa[q] = *(const float4*)(Aptr + (size_t)(t+1)*16 + q*4);
            pb = *(const float4*)(Bptr + (size_t)(t+1)*16*64);
            if (reluA){
#pragma unroll
                for (int q=0;q<4;q++){
                    pa[q].x=fmaxf(pa[q].x,0.f); pa[q].y=fmaxf(pa[q].y,0.f);
                    pa[q].z=fmaxf(pa[q].z,0.f); pa[q].w=fmaxf(pa[q].w,0.f);
                }
            }
        }
#pragma unroll
        for (int kk = 0; kk < 16; kk++){
            float4 a0 = *(const float4*)&As[cb][kk][tm*8];
            float4 a1 = *(const float4*)&As[cb][kk][tm*8+4];
            ulonglong2 b01 = *(const ulonglong2*)&Bs[cb][kk][tn*8];
            ulonglong2 b23 = *(const ulonglong2*)&Bs[cb][kk][tn*8+4];
            unsigned long long bp0 = b01.x, bp1 = b01.y, bp2 = b23.x, bp3 = b23.y;
            float av[8] = {a0.x,a0.y,a0.z,a0.w,a1.x,a1.y,a1.z,a1.w};
#pragma unroll
            for (int i=0;i<8;i++){
                unsigned long long ad;
                PACKF2(ad, av[i], av[i]);
                FMAF2(acc[i][0], ad, bp0);
                FMAF2(acc[i][1], ad, bp1);
                FMAF2(acc[i][2], ad, bp2);
                FMAF2(acc[i][3], ad, bp3);
            }
        }
        if (t+1 < T){
            int nb2 = cb ^ 1;
#pragma unroll
            for (int q=0;q<4;q++){
                As[nb2][q*4+0][tid]=pa[q].x; As[nb2][q*4+1][tid]=pa[q].y;
                As[nb2][q*4+2][tid]=pa[q].z; As[nb2][q*4+3][tid]=pa[q].w;
            }
            *(float4*)&Bs[nb2][brow][bcol] = pb;
            __syncthreads();
        }
    }
#pragma unroll
    for (int i=0;i<8;i++){
        int r = bm + tm*8 + i;
        if (r >= M) continue;
#pragma unroll
        for (int jp=0;jp<4;jp++){
            float lo, hi;
            UNPACKF2(lo, hi, acc[i][jp]);
            *(float2*)&Cc[(size_t)r*64 + tn*8 + jp*2] = make_float2(lo, hi);
        }
    }
}

// ---------------- fp32 GEMM N=32 (layer 0) ----------------
__global__ void gemm32(const float* __restrict__ A, const float* __restrict__ B,
                       float* __restrict__ Cc, int M, int N, int K){
    __shared__ float As[16][64];
    __shared__ float Bs[16][64];
    int tid = threadIdx.x;
    int bm = blockIdx.x * 64;
    int tm = tid >> 4, tn = tid & 15;
    float accv[4][4] = {};
    int arow = bm + (tid >> 2);
    int akq  = (tid & 3) * 4;
    int brow = tid >> 4;
    int bcol = (tid & 15) * 4;
    for (int k0 = 0; k0 < K; k0 += 16){
        float4 a4 = make_float4(0.f,0.f,0.f,0.f);
        if (arow < M) a4 = *(const float4*)(A + (size_t)arow*K + k0 + akq);
        float4 b4 = make_float4(0.f,0.f,0.f,0.f);
        if (bcol < N) b4 = *(const float4*)(B + (size_t)(k0+brow)*N + bcol);
        __syncthreads();
        int lr = tid >> 2;
        As[akq+0][lr] = a4.x; As[akq+1][lr] = a4.y; As[akq+2][lr] = a4.z; As[akq+3][lr] = a4.w;
        *(float4*)&Bs[brow][bcol] = b4;
        __syncthreads();
#pragma unroll
        for (int kk = 0; kk < 16; kk++){
            float4 av = *(const float4*)&As[kk][tm*4];
            float4 bv = *(const float4*)&Bs[kk][tn*4];
            float ar[4] = {av.x, av.y, av.z, av.w};
            float brr[4] = {bv.x, bv.y, bv.z, bv.w};
#pragma unroll
            for (int i=0;i<4;i++)
#pragma unroll
                for (int j=0;j<4;j++) accv[i][j] += ar[i]*brr[j];
        }
    }
#pragma unroll
    for (int i=0;i<4;i++){
        int r = bm + tm*4 + i;
        if (r >= M) continue;
#pragma unroll
        for (int j=0;j<4;j++){
            int c = tn*4 + j;
            if (c < N) Cc[(size_t)r*N + c] = accv[i][j];
        }
    }
}

// ---------------- dot kernels (N<=3) ----------------
__global__ void dotn_kernel(const float* __restrict__ A, const float* __restrict__ B,
                            float* __restrict__ Cc, int M, int N, int K, int reluA){
    extern __shared__ float sBv[];
    int tid = threadIdx.x;
    for (int i = tid; i < K*N; i += blockDim.x) sBv[i] = B[i];
    __syncthreads();
    int w = tid >> 5, lane = tid & 31;
    int r = blockIdx.x * 8 + w;
    if (r >= M) return;
    float a0=0.f, a1=0.f, a2=0.f;
    const float* ap = A + (size_t)r*K;
    for (int k = lane; k < K; k += 32){
        float av = ap[k];
        if (reluA) av = fmaxf(av, 0.f);
        a0 += av * sBv[k*N+0];
        if (N > 1) a1 += av * sBv[k*N+1];
        if (N > 2) a2 += av * sBv[k*N+2];
    }
    for (int off=16; off; off>>=1){
        a0 += __shfl_down_sync(0xffffffffu, a0, off);
        a1 += __shfl_down_sync(0xffffffffu, a1, off);
        a2 += __shfl_down_sync(0xffffffffu, a2, off);
    }
    if (lane == 0){
        Cc[(size_t)r*N+0] = a0;
        if (N > 1) Cc[(size_t)r*N+1] = a1;
        if (N > 2) Cc[(size_t)r*N+2] = a2;
    }
}

__global__ void dotn_bf16(const __nv_bfloat16* __restrict__ Ah, const __nv_bfloat16* __restrict__ Al,
                          const float* __restrict__ B,
                          float* __restrict__ Cc, int M, int K){
    extern __shared__ float sBv[];
    int tid = threadIdx.x;
    for (int i = tid; i < K*3; i += blockDim.x) sBv[i] = B[i];
    __syncthreads();
    int w = tid >> 5, lane = tid & 31;
    int r = blockIdx.x * 8 + w;
    if (r >= M) return;
    float a0=0.f, a1=0.f, a2=0.f;
    const __nv_bfloat16* aph = Ah + (size_t)r*K;
    const __nv_bfloat16* apl = Al + (size_t)r*K;
    for (int k = lane*2; k < K; k += 64){
        __nv_bfloat162 h2 = *(const __nv_bfloat162*)(aph + k);
        __nv_bfloat162 l2 = *(const __nv_bfloat162*)(apl + k);
        float av0 = __bfloat162float(h2.x) + __bfloat162float(l2.x);
        float av1 = __bfloat162float(h2.y) + __bfloat162float(l2.y);
        a0 += av0 * sBv[k*3+0] + av1 * sBv[(k+1)*3+0];
        a1 += av0 * sBv[k*3+1] + av1 * sBv[(k+1)*3+1];
        a2 += av0 * sBv[k*3+2] + av1 * sBv[(k+1)*3+2];
    }
    for (int off=16; off; off>>=1){
        a0 += __shfl_down_sync(0xffffffffu, a0, off);
        a1 += __shfl_down_sync(0xffffffffu, a1, off);
        a2 += __shfl_down_sync(0xffffffffu, a2, off);
    }
    if (lane == 0){
        Cc[(size_t)r*3+0] = a0;
        Cc[(size_t)r*3+1] = a1;
        Cc[(size_t)r*3+2] = a2;
    }
}

// ---------------- elementwise ----------------
__global__ void combine0_kernel(const float* __restrict__ co, const float* __restrict__ cf,
                                const float* __restrict__ feat0,
                                const float* __restrict__ b0o, const float* __restrict__ b0f,
                                const float* __restrict__ wdf, const float* __restrict__ bdf,
                                float* __restrict__ out){
    int e = blockIdx.x*blockDim.x + threadIdx.x;
    if (e >= 9000*96) return;
    int row = e / 96, o = e - row*96;
    int n = row / 3;
    float v;
    if (o < 32) v = co[n*32+o] + b0o[o];
    else if (o < 64) v = cf[(size_t)row*32 + (o-32)] + b0f[o-32];
    else {
        int oo = o - 64;
        v = bdf[oo];
        for (int c=0;c<3;c++) v += feat0[row*3+c]*wdf[c*32+oo];
    }
    out[e] = v;
}

__global__ void combine_kernel(const float* __restrict__ oc, int nsplit,
                               const float* __restrict__ od,
                               const float* __restrict__ bc, const float* __restrict__ bd,
                               const float* __restrict__ prev, float* __restrict__ out, int C){
    int e = blockIdx.x*blockDim.x + threadIdx.x;
    if (e >= 9000*C) return;
    int o = e % C;
    float v = bc[o] + od[e] + bd[o];
    for (int j = 0; j < nsplit; j++) v += oc[(size_t)j*9000*64 + e];
    if (prev) v += prev[e];
    out[e] = v;
}

__global__ void final_kernel(const float* __restrict__ out4, const float* __restrict__ p1,
                             const float* __restrict__ p0, float* __restrict__ dout){
    int e = blockIdx.x*blockDim.x + threadIdx.x;
    if (e >= NF*3) return;
    int n = e/3, d = e - n*3;
    float pc0 = out4[(n*3+0)*3+d] * 0.25f * (1.0f/16.0f);
    float pc1 = out4[(n*3+1)*3+d] * 0.25f;
    float pc2 = out4[(n*3+2)*3+d] * 0.25f;
    float p_c = p1[e] + pc0;
    dout[e] = p_c;
    dout[9000 + e] = (p_c - p0[e]) / 0.1f;
    dout[18000 + n*6 + d]     = pc1;
    dout[18000 + n*6 + 3 + d] = pc2;
}

// ---------------- launch ----------------
extern "C" void kernel_launch(void* const* d_in, const int* in_sizes, int n_in,
                              void* d_out, int out_size){
    const float* v0e  = (const float*)d_in[1];
    const float* p0   = (const float*)d_in[2];
    const float* v0   = (const float*)d_in[3];
    const float* a    = (const float*)d_in[4];
    const float* other= (const float*)d_in[5];
    const float* box  = (const float*)d_in[6];
    const float* boxf = (const float*)d_in[7];
    const float* bmask= (const float*)d_in[9];
    const float* k0f  = (const float*)d_in[10];
    const float* b0f  = (const float*)d_in[11];
    const float* k0o  = (const float*)d_in[12];
    const float* b0o  = (const float*)d_in[13];
    const float* wdf  = (const float*)d_in[14];
    const float* bdf  = (const float*)d_in[15];
    const float *kc[4], *bcp[4], *wd[4], *bdp[4];
    if (in_sizes[18] == 262144){
        for (int i=0;i<4;i++){
            kc[i]=(const float*)d_in[16+2*i]; bcp[i]=(const float*)d_in[17+2*i];
            wd[i]=(const float*)d_in[24+2*i]; bdp[i]=(const float*)d_in[25+2*i];
        }
    } else {
        for (int i=0;i<4;i++){
            kc[i]=(const float*)d_in[16+4*i]; bcp[i]=(const float*)d_in[17+4*i];
            wd[i]=(const float*)d_in[18+4*i]; bdp[i]=(const float*)d_in[19+4*i];
        }
    }
    float* dout = (float*)d_out;

    float *p1, *feat0, *A0, *Abox, *cfb, *cob, *ocb, *odb, *o1, *o2, *fw8, *bw8;
    __nv_bfloat16 *Ahp, *Alp, *Bhp, *Blp;
    int *fcnt, *fidx, *fbase, *bcnt, *bidx, *bbase;
    cudaGetSymbolAddress((void**)&p1, g_p1);
    cudaGetSymbolAddress((void**)&feat0, g_feat0);
    cudaGetSymbolAddress((void**)&A0, g_A0);
    cudaGetSymbolAddress((void**)&Abox, g_Abox);
    cudaGetSymbolAddress((void**)&Ahp, g_Ah);
    cudaGetSymbolAddress((void**)&Alp, g_Al);
    cudaGetSymbolAddress((void**)&Bhp, g_Bh);
    cudaGetSymbolAddress((void**)&Blp, g_Bl);
    cudaGetSymbolAddress((void**)&cfb, g_cf);
    cudaGetSymbolAddress((void**)&cob, g_co);
    cudaGetSymbolAddress((void**)&ocb, g_oc);
    cudaGetSymbolAddress((void**)&odb, g_od);
    cudaGetSymbolAddress((void**)&o1, g_out1);
    cudaGetSymbolAddress((void**)&o2, g_out2);
    cudaGetSymbolAddress((void**)&fw8, g_fw8);
    cudaGetSymbolAddress((void**)&bw8, g_bw8);
    cudaGetSymbolAddress((void**)&fcnt, g_fcnt);
    cudaGetSymbolAddress((void**)&fidx, g_fidx);
    cudaGetSymbolAddress((void**)&fbase, g_fbase);
    cudaGetSymbolAddress((void**)&bcnt, g_bcnt);
    cudaGetSymbolAddress((void**)&bidx, g_bidx);
    cudaGetSymbolAddress((void**)&bbase, g_bbase);

    cudaFuncSetAttribute(scatter_big, cudaFuncAttributeMaxDynamicSharedMemorySize, 80000);
    cudaFuncSetAttribute(gemm_mma,    cudaFuncAttributeMaxDynamicSharedMemorySize, 62000);
    cudaFuncSetAttribute(dotn_kernel, cudaFuncAttributeMaxDynamicSharedMemorySize, 50000);
    cudaFuncSetAttribute(dotn_bf16,   cudaFuncAttributeMaxDynamicSharedMemorySize, 50000);

    prep_kernel<<<(NF+127)/128, 128>>>(p0, v0, a, other, v0e, p1, feat0, dout + 36000);
    neigh_kernel<<<NF, 256>>>(p1, NF, p1, nullptr, 1, fcnt, fidx, fbase, fw8);
    neigh_kernel<<<NF, 256>>>(box, NB, p1, bmask, 0, bcnt, bidx, bbase, bw8);

    // layer 0
    scatter9<<<NF, 96>>>(feat0, fcnt, fidx, fbase, fw8, A0);
    gemm32<<<(9000+63)/64, 256>>>(A0, k0f, cfb, 9000, 32, 192);
    scatter1<<<NF/8, 64>>>(boxf, bcnt, bidx, bbase, bw8, Abox);
    gemm32<<<(3000+63)/64, 256>>>(Abox, k0o, cob, 3000, 32, 64);
    combine0_kernel<<<(9000*96+255)/256, 256>>>(cob, cfb, feat0, b0o, b0f, wdf, bdf, o1);

    int Cin[4] = {96, 64, 64, 64};
    float* cur = o1; float* nxt = o2;
    for (int i=0;i<4;i++){
        int ci = Cin[i];
        int F = 3*ci, F4 = F/4;
        int K = 64*ci;
        int bD = ((F4 + 31)/32)*32;
        scatter_big<<<NF, bD, (size_t)64*F*4>>>(cur, F, ci, fcnt, fidx, fbase, fw8, Ahp, Alp, K);
        if (i < 3){
            convB<<<(64*K+255)/256, 256>>>(kc[i], 64, K, Bhp, Blp);
            gemm_mma<<<dim3(71,2), 256, 61440>>>(Ahp, Alp, Bhp, Blp, ocb, 9000, K);
            gemm_x2<<<dim3(36,1), 256>>>(cur, wd[i], odb, 9000, ci, 1);
            combine_kernel<<<(9000*64+255)/256, 256>>>(ocb, 2, odb,
                bcp[i], bdp[i], (i==1||i==2) ? cur : nullptr, nxt, 64);
        } else {
            dotn_bf16<<<(9000+7)/8, 256, (size_t)K*3*4>>>(Ahp, Alp, kc[3], ocb, 9000, K);
            dotn_kernel<<<(9000+7)/8, 256, (size_t)ci*3*4>>>(cur, wd[3], odb, 9000, 3, ci, 1);
            combine_kernel<<<(27000+255)/256, 256>>>(ocb, 1, odb,
                bcp[3], bdp[3], nullptr, nxt, 3);
        }
        float* t = cur; cur = nxt; nxt = t;
    }
    final_kernel<<<(NF*3+255)/256, 256>>>(cur, p1, p0, dout);
}

// round 11
// speedup vs baseline: 1.4324x; 1.1204x over previous
#include <cuda_runtime.h>
#include <cuda_bf16.h>
#include <cuda_fp16.h>
#include <math.h>
#include <stdint.h>

#define NF 3000
#define NB 1500
#define RAD2 9.0f
#define INV_R (1.0f/3.0f)
#define CAP 256
#define EPSF 1e-8f
#define FOUR_OVER_PI 1.2732395447351628f

// ---------------- static device scratch ----------------
__device__ float g_p1[NF*3];
__device__ float g_feat0[NF*9];
__device__ int   g_fcnt[NF];
__device__ int   g_fidx[NF*64];
__device__ int   g_fbase[NF*64];
__device__ float g_fw8[NF*512];
__device__ int   g_bcnt[NF];
__device__ int   g_bidx[NF*64];
__device__ int   g_bbase[NF*64];
__device__ float g_bw8[NF*512];
__device__ float g_A0[9000*192];
__device__ float g_Abox[NF*64];
__device__ __half g_Ah[(size_t)9088*6144];
__device__ __half g_Bh[64*6144];
__device__ __half g_Bl[64*6144];
__device__ float g_cf[9000*32];
__device__ float g_co[NF*32];
__device__ float g_oc[2*9000*64];
__device__ float g_od[9000*64];
__device__ float g_out1[9000*96];
__device__ float g_out2[9000*96];

// ---------------- helpers ----------------
__device__ __forceinline__ uint32_t smem_u32(const void* p){
    uint32_t a;
    asm("{ .reg .u64 t; cvta.to.shared.u64 t, %1; cvt.u32.u64 %0, t; }" : "=r"(a) : "l"(p));
    return a;
}
__device__ __forceinline__ void ldsm_x4(uint32_t& r0, uint32_t& r1, uint32_t& r2, uint32_t& r3, uint32_t addr){
    asm volatile("ldmatrix.sync.aligned.m8n8.x4.shared.b16 {%0,%1,%2,%3}, [%4];"
        : "=r"(r0), "=r"(r1), "=r"(r2), "=r"(r3) : "r"(addr));
}
__device__ __forceinline__ void ldsm_x2(uint32_t& r0, uint32_t& r1, uint32_t addr){
    asm volatile("ldmatrix.sync.aligned.m8n8.x2.shared.b16 {%0,%1}, [%2];"
        : "=r"(r0), "=r"(r1) : "r"(addr));
}
__device__ __forceinline__ void mma_f16(float* c, const uint32_t* a, const uint32_t* b){
    asm volatile("mma.sync.aligned.m16n8k16.row.col.f32.f16.f16.f32 "
        "{%0,%1,%2,%3}, {%4,%5,%6,%7}, {%8,%9}, {%0,%1,%2,%3};"
        : "+f"(c[0]), "+f"(c[1]), "+f"(c[2]), "+f"(c[3])
        : "r"(a[0]), "r"(a[1]), "r"(a[2]), "r"(a[3]), "r"(b[0]), "r"(b[1]));
}

// ---------------- geometry ----------------
__device__ __forceinline__ float sgnf(float v){ return (v>0.f)?1.f:((v<0.f)?-1.f:0.f); }

__device__ __forceinline__ void ball_to_cube(float x,float y,float z,float&obx,float&oby,float&obz){
    float sq = x*x+y*y+z*z;
    float norm = sqrtf(fmaxf(sq,EPSF));
    float xy_sq = x*x+y*y;
    bool polar = (1.25f*z*z) > xy_sq;
    float s_p = sqrtf(3.0f*norm/(norm+fabsf(z)+EPSF));
    float s_e = norm / sqrtf(fmaxf(xy_sq,EPSF));
    float cx = polar ? x*s_p : x*s_e;
    float cy = polar ? y*s_p : y*s_e;
    float cz = polar ? sgnf(z)*norm : 1.5f*z;
    float nxy = sqrtf(fmaxf(cx*cx+cy*cy,EPSF));
    bool xdom = fabsf(cy) <= fabsf(cx);
    float sx = (fabsf(cx) > EPSF) ? cx : 1.0f;
    float sy = (fabsf(cy) > EPSF) ? cy : 1.0f;
    float bx1 = sgnf(cx)*nxy;
    float by1 = bx1*FOUR_OVER_PI*atanf(cy/sx);
    float by2 = sgnf(cy)*nxy;
    float bx2 = by2*FOUR_OVER_PI*atanf(cx/sy);
    float bx = xdom ? bx1 : bx2;
    float by = xdom ? by1 : by2;
    if (cx*cx+cy*cy < EPSF){ bx=0.f; by=0.f; }
    if (sq < EPSF){ bx=0.f; by=0.f; cz=0.f; }
    obx=bx; oby=by; obz=cz;
}

// ---------------- prep ----------------
__global__ void prep_kernel(const float* __restrict__ p0,const float* __restrict__ v0,
                            const float* __restrict__ a,const float* __restrict__ other,
                            const float* __restrict__ v0e,
                            float* __restrict__ p1,float* __restrict__ feat0,
                            float* __restrict__ outState){
    int i = blockIdx.x*blockDim.x + threadIdx.x;
    if (i >= NF) return;
#pragma unroll
    for (int d=0; d<3; d++){
        float vv0 = v0[i*3+d];
        float v1  = vv0 + 0.1f*a[i*3+d];
        float pp1 = p0[i*3+d] + 0.1f*(vv0+v1)*0.5f;
        p1[i*3+d]        = pp1;
        feat0[i*9+d]     = v1;
        feat0[i*9+3+d]   = other[i*3+d];
        feat0[i*9+6+d]   = v0e[i*3+d];
        outState[i*3+d]  = v0e[i*3+d];
    }
}

// ---------------- neighbor search ----------------
__global__ void neigh_kernel(const float* __restrict__ pin, int Mp,
                             const float* __restrict__ pout,
                             const float* __restrict__ mask, int selfEx,
                             int* __restrict__ cntO, int* __restrict__ idxO,
                             int* __restrict__ baseO, float* __restrict__ w8O){
    __shared__ float cd2[CAP];
    __shared__ int   cid[CAP];
    __shared__ unsigned long long keys[CAP];
    __shared__ int scnt;
    __shared__ int   sM[64];
    __shared__ int   sB[64];
    __shared__ float sW8[64*8];
    __shared__ unsigned skey[64];
    int n = blockIdx.x, tid = threadIdx.x;
    float qx = pout[n*3], qy = pout[n*3+1], qz = pout[n*3+2];
    if (tid==0) scnt = 0;
    __syncthreads();
    for (int m = tid; m < Mp; m += blockDim.x){
        if (selfEx && m==n) continue;
        if (mask && !(mask[m] > 0.f)) continue;
        float dx = pin[m*3]-qx, dy = pin[m*3+1]-qy, dz = pin[m*3+2]-qz;
        float d2 = dx*dx + dy*dy + dz*dz;
        if (d2 <= RAD2){
            int p = atomicAdd(&scnt, 1);
            if (p < CAP){ cd2[p]=d2; cid[p]=m; }
        }
    }
    __syncthreads();
    int cn = min(scnt, CAP);
    for (int t = tid; t < CAP; t += blockDim.x)
        keys[t] = (t < cn) ? ((((unsigned long long)__float_as_uint(cd2[t]))<<32) | (unsigned)cid[t])
                           : 0xFFFFFFFFFFFFFFFFull;
    __syncthreads();
    for (int k = 2; k <= CAP; k <<= 1){
        for (int j = k>>1; j > 0; j >>= 1){
            if (tid < 128){
                int i = ((tid & ~(j-1)) << 1) | (tid & (j-1));
                int ixj = i | j;
                bool asc = ((i & k) == 0);
                unsigned long long av = keys[i], bv = keys[ixj];
                if ((av > bv) == asc){ keys[i]=bv; keys[ixj]=av; }
            }
            __syncthreads();
        }
    }
    int keep = min(cn, 64);
    if (tid==0) cntO[n] = keep;
    for (int t = tid; t < keep; t += blockDim.x){
        unsigned long long key = keys[t];
        int m = (int)(key & 0xFFFFFFFFull);
        float dx = pin[m*3]-qx, dy = pin[m*3+1]-qy, dz = pin[m*3+2]-qz;
        float ux = dx*INV_R, uy = dy*INV_R, uz = dz*INV_R;
        float r2 = ux*ux + uy*uy + uz*uz;
        float t1 = 1.f - r2;
        float win = fminf(fmaxf(t1*t1*t1, 0.f), 1.f);
        float bx, by, bz;
        ball_to_cube(ux, uy, uz, bx, by, bz);
        float cxx = fminf(fmaxf((bx*0.5f+0.5f)*3.f, 0.f), 3.f);
        float cyy = fminf(fmaxf((by*0.5f+0.5f)*3.f, 0.f), 3.f);
        float czz = fminf(fmaxf((bz*0.5f+0.5f)*3.f, 0.f), 3.f);
        int c0x = min((int)floorf(cxx), 2);
        int c0y = min((int)floorf(cyy), 2);
        int c0z = min((int)floorf(czz), 2);
        float fx = cxx - (float)c0x, fy = cyy - (float)c0y, fz = czz - (float)c0z;
        sM[t] = m;
        sB[t] = (c0x*4 + c0y)*4 + c0z;
        float gx[2] = {1.f-fx, fx}, gy[2] = {1.f-fy, fy}, gz[2] = {1.f-fz, fz};
        int jj = 0;
        for (int i2=0;i2<2;i2++) for (int j2=0;j2<2;j2++) for (int l2=0;l2<2;l2++)
            sW8[t*8 + (jj++)] = gx[i2]*gy[j2]*gz[l2]*win;
    }
    for (int t = tid; t < 64; t += blockDim.x)
        skey[t] = (t < keep) ? (unsigned)((sB[t] << 6) | t) : 0xFFFFFFFFu;
    __syncthreads();
    for (int k = 2; k <= 64; k <<= 1){
        for (int j = k>>1; j > 0; j >>= 1){
            if (tid < 32){
                int i = ((tid & ~(j-1)) << 1) | (tid & (j-1));
                int ixj = i | j;
                bool asc = ((i & k) == 0);
                unsigned av = skey[i], bv = skey[ixj];
                if ((av > bv) == asc){ skey[i]=bv; skey[ixj]=av; }
            }
            __syncthreads();
        }
    }
    for (int t = tid; t < keep; t += blockDim.x){
        int s = (int)(skey[t] & 63u);
        idxO[n*64+t]  = sM[s];
        baseO[n*64+t] = sB[s];
#pragma unroll
        for (int j=0;j<8;j++) w8O[n*512 + t*8 + j] = sW8[s*8 + j];
    }
}

__constant__ int c_coff[8] = {0,1,4,5,16,17,20,21};

// ---------------- scatter layer0 fluid (F=9) ----------------
__global__ void scatter9(const float* __restrict__ feats,
                         const int* __restrict__ cnt, const int* __restrict__ nidx,
                         const int* __restrict__ nbase, const float* __restrict__ nw8,
                         float* __restrict__ A){
    __shared__ float planes[8*576];
    __shared__ float sfeat[64*9];
    __shared__ float sW[512];
    __shared__ int   sBase[64];
    __shared__ int   sIdx[64];
    int n = blockIdx.x, tid = threadIdx.x;
    int cn = cnt[n];
    for (int e = tid; e < 8*576; e += 96) planes[e] = 0.f;
    if (tid < cn){ sIdx[tid] = nidx[n*64+tid]; sBase[tid] = nbase[n*64+tid]; }
    for (int e = tid; e < cn*8; e += 96) sW[e] = nw8[n*512+e];
    __syncthreads();
    for (int e = tid; e < cn*9; e += 96){
        int k = e/9, f = e-k*9;
        sfeat[e] = feats[(size_t)sIdx[k]*9 + f];
    }
    __syncthreads();
    if (tid < 72){
        int j = tid/9, f = tid - j*9;
        int off = c_coff[j];
        float r = 0.f; int prevb = -1;
        for (int k = 0; k < cn; k++){
            int b = sBase[k];
            if (b != prevb){
                if (prevb >= 0) planes[j*576 + (prevb+off)*9 + f] += r;
                prevb = b; r = 0.f;
            }
            r += sW[k*8+j]*sfeat[k*9+f];
        }
        if (prevb >= 0) planes[j*576 + (prevb+off)*9 + f] += r;
    }
    __syncthreads();
    for (int e = tid; e < 576; e += 96){
        int l = e/9, f = e-l*9;
        int s = f/3, c = f-s*3;
        float v = 0.f;
#pragma unroll
        for (int j=0;j<8;j++) v += planes[j*576+e];
        A[(size_t)(n*3+s)*192 + l*3 + c] = v;
    }
}

// ---------------- scatter box (F=1) ----------------
__global__ void scatter1(const float* __restrict__ feats,
                         const int* __restrict__ cnt, const int* __restrict__ nidx,
                         const int* __restrict__ nbase, const float* __restrict__ nw8,
                         float* __restrict__ A){
    __shared__ float planes[8*8*64];
    __shared__ float sF[8*64];
    __shared__ float sW[8*512];
    __shared__ int   sBase[8*64];
    __shared__ int   sCn[8];
    int tid = threadIdx.x, nb = blockIdx.x;
    for (int e = tid; e < 8*8*64; e += 64) planes[e] = 0.f;
    for (int e = tid; e < 8*64; e += 64){
        int q = e>>6, k = e&63;
        int n = nb*8+q;
        if (k==0) sCn[q] = cnt[n];
        int cnq = cnt[n];
        if (k < cnq){ sBase[e] = nbase[n*64+k]; sF[e] = feats[nidx[n*64+k]]; }
    }
    for (int e = tid; e < 8*512; e += 64){
        int q = e>>9, r = e&511;
        sW[e] = nw8[(size_t)(nb*8+q)*512 + r];
    }
    __syncthreads();
    {
        int q = tid>>3, j = tid&7;
        int off = c_coff[j];
        int cnq = sCn[q];
        float r = 0.f; int prevb = -1;
        for (int k = 0; k < cnq; k++){
            int b = sBase[q*64+k];
            if (b != prevb){
                if (prevb >= 0) planes[(q*8+j)*64 + prevb+off] += r;
                prevb = b; r = 0.f;
            }
            r += sW[q*512 + k*8 + j]*sF[q*64+k];
        }
        if (prevb >= 0) planes[(q*8+j)*64 + prevb+off] += r;
    }
    __syncthreads();
    for (int e = tid; e < 512; e += 64){
        int q = e>>6, l = e&63;
        float v = 0.f;
#pragma unroll
        for (int j=0;j<8;j++) v += planes[(q*8+j)*64 + l];
        A[(size_t)(nb*8+q)*64 + l] = v;
    }
}

// ---------------- scatter (big): emits fp16 A (relu applied to feats) ----------------
__global__ void scatter_big(const float* __restrict__ feats, int F, int C,
                            const int* __restrict__ cnt, const int* __restrict__ nidx,
                            const int* __restrict__ nbase, const float* __restrict__ nw8,
                            __half* __restrict__ Ah, int K){
    extern __shared__ float acc[];
    __shared__ int sIdx[64]; __shared__ int sBase[64]; __shared__ float sW[512];
    float4* acc4 = (float4*)acc;
    int n = blockIdx.x, tid = threadIdx.x, bd = blockDim.x;
    int F4 = F >> 2;
    int cn = cnt[n];
    for (int e = tid; e < 64*F4; e += bd) acc4[e] = make_float4(0.f,0.f,0.f,0.f);
    for (int e = tid; e < cn; e += bd){ sIdx[e] = nidx[n*64+e]; sBase[e] = nbase[n*64+e]; }
    for (int e = tid; e < cn*8; e += bd) sW[e] = nw8[n*512+e];
    __syncthreads();
    int f4 = tid;
    if (f4 < F4){
        float4 r[8];
        int prevb = -1;
        for (int k = 0; k < cn; k++){
            int b = sBase[k];
            if (b != prevb){
                if (prevb >= 0){
#pragma unroll
                    for (int j=0;j<8;j++){
                        int ai = (prevb + c_coff[j])*F4 + f4;
                        float4 t = acc4[ai];
                        t.x += r[j].x; t.y += r[j].y; t.z += r[j].z; t.w += r[j].w;
                        acc4[ai] = t;
                    }
                }
                prevb = b;
#pragma unroll
                for (int j=0;j<8;j++) r[j] = make_float4(0.f,0.f,0.f,0.f);
            }
            float4 fv = ((const float4*)(feats + (size_t)sIdx[k]*F))[f4];
            fv.x = fmaxf(fv.x,0.f); fv.y = fmaxf(fv.y,0.f);
            fv.z = fmaxf(fv.z,0.f); fv.w = fmaxf(fv.w,0.f);
#pragma unroll
            for (int j=0;j<8;j++){
                float w = sW[k*8+j];
                r[j].x += w*fv.x; r[j].y += w*fv.y; r[j].z += w*fv.z; r[j].w += w*fv.w;
            }
        }
        if (prevb >= 0){
#pragma unroll
            for (int j=0;j<8;j++){
                int ai = (prevb + c_coff[j])*F4 + f4;
                float4 t = acc4[ai];
                t.x += r[j].x; t.y += r[j].y; t.z += r[j].z; t.w += r[j].w;
                acc4[ai] = t;
            }
        }
    }
    __syncthreads();
    for (int e4 = tid; e4 < 64*F4; e4 += bd){
        int l = e4 / F4, fl = e4 - l*F4;
        int f = fl*4;
        int s = f / C, c = f - s*C;
        float4 v = acc4[e4];
        size_t base = (size_t)(n*3+s)*K + l*C + c;
        __half2 h01 = __floats2half2_rn(v.x, v.y);
        __half2 h23 = __floats2half2_rn(v.z, v.w);
        *(__half2*)(Ah+base)   = h01;
        *(__half2*)(Ah+base+2) = h23;
    }
}

// ---------------- B conversion: [K,N] fp32 -> [64][K] fp16 hi/lo (n-major, zero pad) ----------------
__global__ void convB(const float* __restrict__ B, int N, int K,
                      __half* __restrict__ BhT, __half* __restrict__ BlT){
    int e = blockIdx.x*blockDim.x + threadIdx.x;
    if (e >= 64*K) return;
    int n = e / K, k = e - n*K;
    float v = (n < N) ? B[(size_t)k*N + n] : 0.f;
    __half h = __float2half_rn(v);
    BhT[e] = h;
    BlT[e] = __float2half_rn(v - __half2float(h));
}

// ---------------- fp16 MMA GEMM: C[M,64] = A[M,K] @ (Bh+Bl)[64,K]^T ----------------
// 128x64 CTA tile, 8 warps (warp = 32x32), KC=32 chunks double-buffered.
__global__ __launch_bounds__(256) void gemm_mma(const __half* __restrict__ Ah,
                                                const __half* __restrict__ Bh,
                                                const __half* __restrict__ Bl,
                                                float* __restrict__ Cc, int M, int K){
    extern __shared__ __half sm[];
    const int RS = 40;                 // row stride in halves (32 + 8 pad, conflict-free LDSM)
    const int OFF_BH = 128*RS;         // 5120
    const int OFF_BL = 128*RS + 64*RS; // 7680
    const int BUFSZ  = 128*RS + 2*64*RS; // 10240 halves per buffer
    int tid = threadIdx.x;
    int bm = blockIdx.x*128;
    int kLen = K / gridDim.y;
    int kBeg = blockIdx.y*kLen;
    int T = kLen >> 5;
    float* Cout = Cc + (size_t)blockIdx.y * M * 64;

    int arow = tid >> 1, ahalf = tid & 1;              // 2 thr/row, 16 halves each
    const __half* AG = Ah + (size_t)(bm+arow)*K + kBeg + ahalf*16;
    int brow = tid >> 2, bq = tid & 3;                 // 4 thr/row, 8 halves each
    const __half* BhG = Bh + (size_t)brow*K + kBeg + bq*8;
    const __half* BlG = Bl + (size_t)brow*K + kBeg + bq*8;

    uint32_t sbase = smem_u32(sm);
    int wid = tid >> 5, lane = tid & 31;
    int wm = wid & 3, wn = wid >> 2;

    uint4 ra0, ra1, rbh, rbl;
    ra0 = *(const uint4*)(AG);     ra1 = *(const uint4*)(AG + 8);
    rbh = *(const uint4*)(BhG);    rbl = *(const uint4*)(BlG);
    {
        __half* buf = sm;
        *(uint4*)(buf + arow*RS + ahalf*16)     = ra0;
        *(uint4*)(buf + arow*RS + ahalf*16 + 8) = ra1;
        *(uint4*)(buf + OFF_BH + brow*RS + bq*8) = rbh;
        *(uint4*)(buf + OFF_BL + brow*RS + bq*8) = rbl;
    }
    __syncthreads();

    float acc[2][4][4];
#pragma unroll
    for (int mt=0;mt<2;mt++)
#pragma unroll
        for (int nt=0;nt<4;nt++)
#pragma unroll
            for (int q=0;q<4;q++) acc[mt][nt][q] = 0.f;

    for (int t = 0; t < T; t++){
        if (t+1 < T){
            ra0 = *(const uint4*)(AG + (size_t)(t+1)*32);
            ra1 = *(const uint4*)(AG + (size_t)(t+1)*32 + 8);
            rbh = *(const uint4*)(BhG + (size_t)(t+1)*32);
            rbl = *(const uint4*)(BlG + (size_t)(t+1)*32);
        }
        uint32_t bufo = (uint32_t)((t & 1) * BUFSZ) * 2;   // byte offset
#pragma unroll
        for (int ks = 0; ks < 2; ks++){
            int k0 = ks*16;
            uint32_t af[2][4];
#pragma unroll
            for (int mt=0;mt<2;mt++){
                int row = wm*32 + mt*16 + (lane & 15);
                int col = k0 + (lane >> 4)*8;
                uint32_t addr = sbase + bufo + (uint32_t)(row*RS + col)*2;
                ldsm_x4(af[mt][0], af[mt][1], af[mt][2], af[mt][3], addr);
            }
            uint32_t bfh[4][2], bfl[4][2];
#pragma unroll
            for (int nt=0;nt<4;nt++){
                int row = wn*32 + nt*8 + (lane & 7);
                int col = k0 + ((lane >> 3) & 1)*8;
                uint32_t addr = sbase + bufo + (uint32_t)(OFF_BH + row*RS + col)*2;
                ldsm_x2(bfh[nt][0], bfh[nt][1], addr);
                ldsm_x2(bfl[nt][0], bfl[nt][1], addr + (OFF_BL-OFF_BH)*2);
            }
#pragma unroll
            for (int mt=0;mt<2;mt++)
#pragma unroll
                for (int nt=0;nt<4;nt++){
                    mma_f16(acc[mt][nt], af[mt], bfh[nt]);
                    mma_f16(acc[mt][nt], af[mt], bfl[nt]);
                }
        }
        if (t+1 < T){
            __half* buf = sm + ((t+1) & 1) * BUFSZ;
            *(uint4*)(buf + arow*RS + ahalf*16)     = ra0;
            *(uint4*)(buf + arow*RS + ahalf*16 + 8) = ra1;
            *(uint4*)(buf + OFF_BH + brow*RS + bq*8) = rbh;
            *(uint4*)(buf + OFF_BL + brow*RS + bq*8) = rbl;
            __syncthreads();
        }
    }
#pragma unroll
    for (int mt=0;mt<2;mt++){
#pragma unroll
        for (int nt=0;nt<4;nt++){
            int r0 = bm + wm*32 + mt*16 + (lane >> 2);
            int c0 = wn*32 + nt*8 + (lane & 3)*2;
            if (r0 < M)     *(float2*)&Cout[(size_t)r0*64 + c0]     = make_float2(acc[mt][nt][0], acc[mt][nt][1]);
            if (r0+8 < M)   *(float2*)&Cout[(size_t)(r0+8)*64 + c0] = make_float2(acc[mt][nt][2], acc[mt][nt][3]);
        }
    }
}

// ---- packed-f32x2 GEMM (dense branch, small K) ----
#define PACKF2(d, lo, hi)  asm("mov.b64 %0, {%1,%2};" : "=l"(d) : "f"(lo), "f"(hi))
#define FMAF2(acc, a, b)   asm("fma.rn.f32x2 %0, %1, %2, %0;" : "+l"(acc) : "l"(a), "l"(b))
#define UNPACKF2(lo, hi, v) asm("mov.b64 {%0,%1}, %2;" : "=f"(lo), "=f"(hi) : "l"(v))

__global__ __launch_bounds__(256) void gemm_x2(const float* __restrict__ A,
                                               const float* __restrict__ B,
                                               float* __restrict__ Cc,
                                               int M, int K, int reluA){
    __shared__ float As[2][16][256];
    __shared__ float Bs[2][16][64];
    int tid = threadIdx.x;
    int bm = blockIdx.x * 256;
    int T = K >> 4;
    int tm = tid >> 3, tn = tid & 7;
    int arow = min(bm + tid, M-1);
    const float* Aptr = A + (size_t)arow*K;
    int brow = tid >> 4, bcol = (tid & 15)*4;
    const float* Bptr = B + (size_t)brow*64 + bcol;

    float4 pa[4], pb;
#pragma unroll
    for (int q=0;q<4;q++) pa[q] = *(const float4*)(Aptr + q*4);
    pb = *(const float4*)(Bptr);
    if (reluA){
#pragma unroll
        for (int q=0;q<4;q++){
            pa[q].x=fmaxf(pa[q].x,0.f); pa[q].y=fmaxf(pa[q].y,0.f);
            pa[q].z=fmaxf(pa[q].z,0.f); pa[q].w=fmaxf(pa[q].w,0.f);
        }
    }
#pragma unroll
    for (int q=0;q<4;q++){
        As[0][q*4+0][tid]=pa[q].x; As[0][q*4+1][tid]=pa[q].y;
        As[0][q*4+2][tid]=pa[q].z; As[0][q*4+3][tid]=pa[q].w;
    }
    *(float4*)&Bs[0][brow][bcol] = pb;
    __syncthreads();

    unsigned long long acc[8][4] = {};
    for (int t = 0; t < T; t++){
        int cb = t & 1;
        if (t+1 < T){
#pragma unroll
            for (int q=0;q<4;q++) pa[q] = *(const float4*)(Aptr + (size_t)(t+1)*16 + q*4);
            pb = *(const float4*)(Bptr + (size_t)(t+1)*16*64);
            if (reluA){
#pragma unroll
                for (int q=0;q<4;q++){
                    pa[q].x=fmaxf(pa[q].x,0.f); pa[q].y=fmaxf(pa[q].y,0.f);
                    pa[q].z=fmaxf(pa[q].z,0.f); pa[q].w=fmaxf(pa[q].w,0.f);
                }
            }
        }
#pragma unroll
        for (int kk = 0; kk < 16; kk++){
            float4 a0 = *(const float4*)&As[cb][kk][tm*8];
            float4 a1 = *(const float4*)&As[cb][kk][tm*8+4];
            ulonglong2 b01 = *(const ulonglong2*)&Bs[cb][kk][tn*8];
            ulonglong2 b23 = *(const ulonglong2*)&Bs[cb][kk][tn*8+4];
            unsigned long long bp0 = b01.x, bp1 = b01.y, bp2 = b23.x, bp3 = b23.y;
            float av[8] = {a0.x,a0.y,a0.z,a0.w,a1.x,a1.y,a1.z,a1.w};
#pragma unroll
            for (int i=0;i<8;i++){
                unsigned long long ad;
                PACKF2(ad, av[i], av[i]);
                FMAF2(acc[i][0], ad, bp0);
                FMAF2(acc[i][1], ad, bp1);
                FMAF2(acc[i][2], ad, bp2);
                FMAF2(acc[i][3], ad, bp3);
            }
        }
        if (t+1 < T){
            int nb2 = cb ^ 1;
#pragma unroll
            for (int q=0;q<4;q++){
                As[nb2][q*4+0][tid]=pa[q].x; As[nb2][q*4+1][tid]=pa[q].y;
                As[nb2][q*4+2][tid]=pa[q].z; As[nb2][q*4+3][tid]=pa[q].w;
            }
            *(float4*)&Bs[nb2][brow][bcol] = pb;
            __syncthreads();
        }
    }
#pragma unroll
    for (int i=0;i<8;i++){
        int r = bm + tm*8 + i;
        if (r >= M) continue;
#pragma unroll
        for (int jp=0;jp<4;jp++){
            float lo, hi;
            UNPACKF2(lo, hi, acc[i][jp]);
            *(float2*)&Cc[(size_t)r*64 + tn*8 + jp*2] = make_float2(lo, hi);
        }
    }
}

// ---------------- fp32 GEMM N=32 (layer 0) ----------------
__global__ void gemm32(const float* __restrict__ A, const float* __restrict__ B,
                       float* __restrict__ Cc, int M, int N, int K){
    __shared__ float As[16][64];
    __shared__ float Bs[16][64];
    int tid = threadIdx.x;
    int bm = blockIdx.x * 64;
    int tm = tid >> 4, tn = tid & 15;
    float accv[4][4] = {};
    int arow = bm + (tid >> 2);
    int akq  = (tid & 3) * 4;
    int brow = tid >> 4;
    int bcol = (tid & 15) * 4;
    for (int k0 = 0; k0 < K; k0 += 16){
        float4 a4 = make_float4(0.f,0.f,0.f,0.f);
        if (arow < M) a4 = *(const float4*)(A + (size_t)arow*K + k0 + akq);
        float4 b4 = make_float4(0.f,0.f,0.f,0.f);
        if (bcol < N) b4 = *(const float4*)(B + (size_t)(k0+brow)*N + bcol);
        __syncthreads();
        int lr = tid >> 2;
        As[akq+0][lr] = a4.x; As[akq+1][lr] = a4.y; As[akq+2][lr] = a4.z; As[akq+3][lr] = a4.w;
        *(float4*)&Bs[brow][bcol] = b4;
        __syncthreads();
#pragma unroll
        for (int kk = 0; kk < 16; kk++){
            float4 av = *(const float4*)&As[kk][tm*4];
            float4 bv = *(const float4*)&Bs[kk][tn*4];
            float ar[4] = {av.x, av.y, av.z, av.w};
            float brr[4] = {bv.x, bv.y, bv.z, bv.w};
#pragma unroll
            for (int i=0;i<4;i++)
#pragma unroll
                for (int j=0;j<4;j++) accv[i][j] += ar[i]*brr[j];
        }
    }
#pragma unroll
    for (int i=0;i<4;i++){
        int r = bm + tm*4 + i;
        if (r >= M) continue;
#pragma unroll
        for (int j=0;j<4;j++){
            int c = tn*4 + j;
            if (c < N) Cc[(size_t)r*N + c] = accv[i][j];
        }
    }
}

// ---------------- dot kernels (N<=3) ----------------
__global__ void dotn_kernel(const float* __restrict__ A, const float* __restrict__ B,
                            float* __restrict__ Cc, int M, int N, int K, int reluA){
    extern __shared__ float sBv[];
    int tid = threadIdx.x;
    for (int i = tid; i < K*N; i += blockDim.x) sBv[i] = B[i];
    __syncthreads();
    int w = tid >> 5, lane = tid & 31;
    int r = blockIdx.x * 8 + w;
    if (r >= M) return;
    float a0=0.f, a1=0.f, a2=0.f;
    const float* ap = A + (size_t)r*K;
    for (int k = lane; k < K; k += 32){
        float av = ap[k];
        if (reluA) av = fmaxf(av, 0.f);
        a0 += av * sBv[k*N+0];
        if (N > 1) a1 += av * sBv[k*N+1];
        if (N > 2) a2 += av * sBv[k*N+2];
    }
    for (int off=16; off; off>>=1){
        a0 += __shfl_down_sync(0xffffffffu, a0, off);
        a1 += __shfl_down_sync(0xffffffffu, a1, off);
        a2 += __shfl_down_sync(0xffffffffu, a2, off);
    }
    if (lane == 0){
        Cc[(size_t)r*N+0] = a0;
        if (N > 1) Cc[(size_t)r*N+1] = a1;
        if (N > 2) Cc[(size_t)r*N+2] = a2;
    }
}

__global__ void dotn_f16(const __half* __restrict__ Ah, const float* __restrict__ B,
                         float* __restrict__ Cc, int M, int K){
    extern __shared__ float sBv[];
    int tid = threadIdx.x;
    for (int i = tid; i < K*3; i += blockDim.x) sBv[i] = B[i];
    __syncthreads();
    int w = tid >> 5, lane = tid & 31;
    int r = blockIdx.x * 8 + w;
    if (r >= M) return;
    float a0=0.f, a1=0.f, a2=0.f;
    const __half* ap = Ah + (size_t)r*K;
    for (int k = lane*2; k < K; k += 64){
        __half2 h2 = *(const __half2*)(ap + k);
        float av0 = __half2float(h2.x);
        float av1 = __half2float(h2.y);
        a0 += av0 * sBv[k*3+0] + av1 * sBv[(k+1)*3+0];
        a1 += av0 * sBv[k*3+1] + av1 * sBv[(k+1)*3+1];
        a2 += av0 * sBv[k*3+2] + av1 * sBv[(k+1)*3+2];
    }
    for (int off=16; off; off>>=1){
        a0 += __shfl_down_sync(0xffffffffu, a0, off);
        a1 += __shfl_down_sync(0xffffffffu, a1, off);
        a2 += __shfl_down_sync(0xffffffffu, a2, off);
    }
    if (lane == 0){
        Cc[(size_t)r*3+0] = a0;
        Cc[(size_t)r*3+1] = a1;
        Cc[(size_t)r*3+2] = a2;
    }
}

// ---------------- elementwise ----------------
__global__ void combine0_kernel(const float* __restrict__ co, const float* __restrict__ cf,
                                const float* __restrict__ feat0,
                                const float* __restrict__ b0o, const float* __restrict__ b0f,
                                const float* __restrict__ wdf, const float* __restrict__ bdf,
                                float* __restrict__ out){
    int e = blockIdx.x*blockDim.x + threadIdx.x;
    if (e >= 9000*96) return;
    int row = e / 96, o = e - row*96;
    int n = row / 3;
    float v;
    if (o < 32) v = co[n*32+o] + b0o[o];
    else if (o < 64) v = cf[(size_t)row*32 + (o-32)] + b0f[o-32];
    else {
        int oo = o - 64;
        v = bdf[oo];
        for (int c=0;c<3;c++) v += feat0[row*3+c]*wdf[c*32+oo];
    }
    out[e] = v;
}

__global__ void combine_kernel(const float* __restrict__ oc, int nsplit,
                               const float* __restrict__ od,
                               const float* __restrict__ bc, const float* __restrict__ bd,
                               const float* __restrict__ prev, float* __restrict__ out, int C){
    int e = blockIdx.x*blockDim.x + threadIdx.x;
    if (e >= 9000*C) return;
    int o = e % C;
    float v = bc[o] + od[e] + bd[o];
    for (int j = 0; j < nsplit; j++) v += oc[(size_t)j*9000*64 + e];
    if (prev) v += prev[e];
    out[e] = v;
}

__global__ void final_kernel(const float* __restrict__ out4, const float* __restrict__ p1,
                             const float* __restrict__ p0, float* __restrict__ dout){
    int e = blockIdx.x*blockDim.x + threadIdx.x;
    if (e >= NF*3) return;
    int n = e/3, d = e - n*3;
    float pc0 = out4[(n*3+0)*3+d] * 0.25f * (1.0f/16.0f);
    float pc1 = out4[(n*3+1)*3+d] * 0.25f;
    float pc2 = out4[(n*3+2)*3+d] * 0.25f;
    float p_c = p1[e] + pc0;
    dout[e] = p_c;
    dout[9000 + e] = (p_c - p0[e]) / 0.1f;
    dout[18000 + n*6 + d]     = pc1;
    dout[18000 + n*6 + 3 + d] = pc2;
}

// ---------------- launch ----------------
extern "C" void kernel_launch(void* const* d_in, const int* in_sizes, int n_in,
                              void* d_out, int out_size){
    const float* v0e  = (const float*)d_in[1];
    const float* p0   = (const float*)d_in[2];
    const float* v0   = (const float*)d_in[3];
    const float* a    = (const float*)d_in[4];
    const float* other= (const float*)d_in[5];
    const float* box  = (const float*)d_in[6];
    const float* boxf = (const float*)d_in[7];
    const float* bmask= (const float*)d_in[9];
    const float* k0f  = (const float*)d_in[10];
    const float* b0f  = (const float*)d_in[11];
    const float* k0o  = (const float*)d_in[12];
    const float* b0o  = (const float*)d_in[13];
    const float* wdf  = (const float*)d_in[14];
    const float* bdf  = (const float*)d_in[15];
    const float *kc[4], *bcp[4], *wd[4], *bdp[4];
    if (in_sizes[18] == 262144){
        for (int i=0;i<4;i++){
            kc[i]=(const float*)d_in[16+2*i]; bcp[i]=(const float*)d_in[17+2*i];
            wd[i]=(const float*)d_in[24+2*i]; bdp[i]=(const float*)d_in[25+2*i];
        }
    } else {
        for (int i=0;i<4;i++){
            kc[i]=(const float*)d_in[16+4*i]; bcp[i]=(const float*)d_in[17+4*i];
            wd[i]=(const float*)d_in[18+4*i]; bdp[i]=(const float*)d_in[19+4*i];
        }
    }
    float* dout = (float*)d_out;

    float *p1, *feat0, *A0, *Abox, *cfb, *cob, *ocb, *odb, *o1, *o2, *fw8, *bw8;
    __half *Ahp, *Bhp, *Blp;
    int *fcnt, *fidx, *fbase, *bcnt, *bidx, *bbase;
    cudaGetSymbolAddress((void**)&p1, g_p1);
    cudaGetSymbolAddress((void**)&feat0, g_feat0);
    cudaGetSymbolAddress((void**)&A0, g_A0);
    cudaGetSymbolAddress((void**)&Abox, g_Abox);
    cudaGetSymbolAddress((void**)&Ahp, g_Ah);
    cudaGetSymbolAddress((void**)&Bhp, g_Bh);
    cudaGetSymbolAddress((void**)&Blp, g_Bl);
    cudaGetSymbolAddress((void**)&cfb, g_cf);
    cudaGetSymbolAddress((void**)&cob, g_co);
    cudaGetSymbolAddress((void**)&ocb, g_oc);
    cudaGetSymbolAddress((void**)&odb, g_od);
    cudaGetSymbolAddress((void**)&o1, g_out1);
    cudaGetSymbolAddress((void**)&o2, g_out2);
    cudaGetSymbolAddress((void**)&fw8, g_fw8);
    cudaGetSymbolAddress((void**)&bw8, g_bw8);
    cudaGetSymbolAddress((void**)&fcnt, g_fcnt);
    cudaGetSymbolAddress((void**)&fidx, g_fidx);
    cudaGetSymbolAddress((void**)&fbase, g_fbase);
    cudaGetSymbolAddress((void**)&bcnt, g_bcnt);
    cudaGetSymbolAddress((void**)&bidx, g_bidx);
    cudaGetSymbolAddress((void**)&bbase, g_bbase);

    cudaFuncSetAttribute(scatter_big, cudaFuncAttributeMaxDynamicSharedMemorySize, 80000);
    cudaFuncSetAttribute(gemm_mma,    cudaFuncAttributeMaxDynamicSharedMemorySize, 41000);
    cudaFuncSetAttribute(dotn_kernel, cudaFuncAttributeMaxDynamicSharedMemorySize, 50000);
    cudaFuncSetAttribute(dotn_f16,    cudaFuncAttributeMaxDynamicSharedMemorySize, 50000);

    prep_kernel<<<(NF+127)/128, 128>>>(p0, v0, a, other, v0e, p1, feat0, dout + 36000);
    neigh_kernel<<<NF, 256>>>(p1, NF, p1, nullptr, 1, fcnt, fidx, fbase, fw8);
    neigh_kernel<<<NF, 256>>>(box, NB, p1, bmask, 0, bcnt, bidx, bbase, bw8);

    // layer 0
    scatter9<<<NF, 96>>>(feat0, fcnt, fidx, fbase, fw8, A0);
    gemm32<<<(9000+63)/64, 256>>>(A0, k0f, cfb, 9000, 32, 192);
    scatter1<<<NF/8, 64>>>(boxf, bcnt, bidx, bbase, bw8, Abox);
    gemm32<<<(3000+63)/64, 256>>>(Abox, k0o, cob, 3000, 32, 64);
    combine0_kernel<<<(9000*96+255)/256, 256>>>(cob, cfb, feat0, b0o, b0f, wdf, bdf, o1);

    int Cin[4] = {96, 64, 64, 64};
    float* cur = o1; float* nxt = o2;
    for (int i=0;i<4;i++){
        int ci = Cin[i];
        int F = 3*ci, F4 = F/4;
        int K = 64*ci;
        int bD = ((F4 + 31)/32)*32;
        scatter_big<<<NF, bD, (size_t)64*F*4>>>(cur, F, ci, fcnt, fidx, fbase, fw8, Ahp, K);
        if (i < 3){
            convB<<<(64*K+255)/256, 256>>>(kc[i], 64, K, Bhp, Blp);
            gemm_mma<<<dim3(71,2), 256, 40960>>>(Ahp, Bhp, Blp, ocb, 9000, K);
            gemm_x2<<<dim3(36,1), 256>>>(cur, wd[i], odb, 9000, ci, 1);
            combine_kernel<<<(9000*64+255)/256, 256>>>(ocb, 2, odb,
                bcp[i], bdp[i], (i==1||i==2) ? cur : nullptr, nxt, 64);
        } else {
            dotn_f16<<<(9000+7)/8, 256, (size_t)K*3*4>>>(Ahp, kc[3], ocb, 9000, K);
            dotn_kernel<<<(9000+7)/8, 256, (size_t)ci*3*4>>>(cur, wd[3], odb, 9000, 3, ci, 1);
            combine_kernel<<<(27000+255)/256, 256>>>(ocb, 1, odb,
                bcp[3], bdp[3], nullptr, nxt, 3);
        }
        float* t = cur; cur = nxt; nxt = t;
    }
    final_kernel<<<(NF*3+255)/256, 256>>>(cur, p1, p0, dout);
}

// round 12
// speedup vs baseline: 1.5625x; 1.0908x over previous
#include <cuda_runtime.h>
#include <cuda_fp16.h>
#include <math.h>
#include <stdint.h>

#define NF 3000
#define NB 1500
#define RAD2 9.0f
#define INV_R (1.0f/3.0f)
#define CAP 256
#define EPSF 1e-8f
#define FOUR_OVER_PI 1.2732395447351628f

// ---------------- static device scratch ----------------
__device__ float g_p1[NF*3];
__device__ float g_feat0[NF*9];
__device__ int   g_fcnt[NF];
__device__ int   g_fidx[NF*64];
__device__ int   g_fbase[NF*64];
__device__ float g_fw8[NF*512];
__device__ int   g_bcnt[NF];
__device__ int   g_bidx[NF*64];
__device__ int   g_bbase[NF*64];
__device__ float g_bw8[NF*512];
__device__ float g_A0[9000*192];
__device__ float g_Abox[NF*64];
__device__ __half g_Ah[(size_t)9088*6400];
__device__ __half g_Bh[64*14592];
__device__ float g_cf[9000*32];
__device__ float g_co[NF*32];
__device__ float g_oc[2*9000*64];
__device__ float g_out1[9000*96];
__device__ float g_out2[9000*96];

// ---------------- helpers ----------------
__device__ __forceinline__ uint32_t smem_u32(const void* p){
    uint32_t a;
    asm("{ .reg .u64 t; cvta.to.shared.u64 t, %1; cvt.u32.u64 %0, t; }" : "=r"(a) : "l"(p));
    return a;
}
__device__ __forceinline__ void ldsm_x4(uint32_t& r0, uint32_t& r1, uint32_t& r2, uint32_t& r3, uint32_t addr){
    asm volatile("ldmatrix.sync.aligned.m8n8.x4.shared.b16 {%0,%1,%2,%3}, [%4];"
        : "=r"(r0), "=r"(r1), "=r"(r2), "=r"(r3) : "r"(addr));
}
__device__ __forceinline__ void ldsm_x2(uint32_t& r0, uint32_t& r1, uint32_t addr){
    asm volatile("ldmatrix.sync.aligned.m8n8.x2.shared.b16 {%0,%1}, [%2];"
        : "=r"(r0), "=r"(r1) : "r"(addr));
}
__device__ __forceinline__ void mma_f16(float* c, const uint32_t* a, const uint32_t* b){
    asm volatile("mma.sync.aligned.m16n8k16.row.col.f32.f16.f16.f32 "
        "{%0,%1,%2,%3}, {%4,%5,%6,%7}, {%8,%9}, {%0,%1,%2,%3};"
        : "+f"(c[0]), "+f"(c[1]), "+f"(c[2]), "+f"(c[3])
        : "r"(a[0]), "r"(a[1]), "r"(a[2]), "r"(a[3]), "r"(b[0]), "r"(b[1]));
}

// ---------------- geometry ----------------
__device__ __forceinline__ float sgnf(float v){ return (v>0.f)?1.f:((v<0.f)?-1.f:0.f); }

__device__ __forceinline__ void ball_to_cube(float x,float y,float z,float&obx,float&oby,float&obz){
    float sq = x*x+y*y+z*z;
    float norm = sqrtf(fmaxf(sq,EPSF));
    float xy_sq = x*x+y*y;
    bool polar = (1.25f*z*z) > xy_sq;
    float s_p = sqrtf(3.0f*norm/(norm+fabsf(z)+EPSF));
    float s_e = norm / sqrtf(fmaxf(xy_sq,EPSF));
    float cx = polar ? x*s_p : x*s_e;
    float cy = polar ? y*s_p : y*s_e;
    float cz = polar ? sgnf(z)*norm : 1.5f*z;
    float nxy = sqrtf(fmaxf(cx*cx+cy*cy,EPSF));
    bool xdom = fabsf(cy) <= fabsf(cx);
    float sx = (fabsf(cx) > EPSF) ? cx : 1.0f;
    float sy = (fabsf(cy) > EPSF) ? cy : 1.0f;
    float bx1 = sgnf(cx)*nxy;
    float by1 = bx1*FOUR_OVER_PI*atanf(cy/sx);
    float by2 = sgnf(cy)*nxy;
    float bx2 = by2*FOUR_OVER_PI*atanf(cx/sy);
    float bx = xdom ? bx1 : bx2;
    float by = xdom ? by1 : by2;
    if (cx*cx+cy*cy < EPSF){ bx=0.f; by=0.f; }
    if (sq < EPSF){ bx=0.f; by=0.f; cz=0.f; }
    obx=bx; oby=by; obz=cz;
}

// ---------------- prep ----------------
__global__ void prep_kernel(const float* __restrict__ p0,const float* __restrict__ v0,
                            const float* __restrict__ a,const float* __restrict__ other,
                            const float* __restrict__ v0e,
                            float* __restrict__ p1,float* __restrict__ feat0,
                            float* __restrict__ outState){
    int i = blockIdx.x*blockDim.x + threadIdx.x;
    if (i >= NF) return;
#pragma unroll
    for (int d=0; d<3; d++){
        float vv0 = v0[i*3+d];
        float v1  = vv0 + 0.1f*a[i*3+d];
        float pp1 = p0[i*3+d] + 0.1f*(vv0+v1)*0.5f;
        p1[i*3+d]        = pp1;
        feat0[i*9+d]     = v1;
        feat0[i*9+3+d]   = other[i*3+d];
        feat0[i*9+6+d]   = v0e[i*3+d];
        outState[i*3+d]  = v0e[i*3+d];
    }
}

// ---------------- neighbor search ----------------
__global__ void neigh_kernel(const float* __restrict__ pin, int Mp,
                             const float* __restrict__ pout,
                             const float* __restrict__ mask, int selfEx,
                             int* __restrict__ cntO, int* __restrict__ idxO,
                             int* __restrict__ baseO, float* __restrict__ w8O){
    __shared__ float cd2[CAP];
    __shared__ int   cid[CAP];
    __shared__ unsigned long long keys[CAP];
    __shared__ int scnt;
    __shared__ int   sM[64];
    __shared__ int   sB[64];
    __shared__ float sW8[64*8];
    __shared__ unsigned skey[64];
    int n = blockIdx.x, tid = threadIdx.x;
    float qx = pout[n*3], qy = pout[n*3+1], qz = pout[n*3+2];
    if (tid==0) scnt = 0;
    __syncthreads();
    for (int m = tid; m < Mp; m += blockDim.x){
        if (selfEx && m==n) continue;
        if (mask && !(mask[m] > 0.f)) continue;
        float dx = pin[m*3]-qx, dy = pin[m*3+1]-qy, dz = pin[m*3+2]-qz;
        float d2 = dx*dx + dy*dy + dz*dz;
        if (d2 <= RAD2){
            int p = atomicAdd(&scnt, 1);
            if (p < CAP){ cd2[p]=d2; cid[p]=m; }
        }
    }
    __syncthreads();
    int cn = min(scnt, CAP);
    for (int t = tid; t < CAP; t += blockDim.x)
        keys[t] = (t < cn) ? ((((unsigned long long)__float_as_uint(cd2[t]))<<32) | (unsigned)cid[t])
                           : 0xFFFFFFFFFFFFFFFFull;
    __syncthreads();
    for (int k = 2; k <= CAP; k <<= 1){
        for (int j = k>>1; j > 0; j >>= 1){
            if (tid < 128){
                int i = ((tid & ~(j-1)) << 1) | (tid & (j-1));
                int ixj = i | j;
                bool asc = ((i & k) == 0);
                unsigned long long av = keys[i], bv = keys[ixj];
                if ((av > bv) == asc){ keys[i]=bv; keys[ixj]=av; }
            }
            __syncthreads();
        }
    }
    int keep = min(cn, 64);
    if (tid==0) cntO[n] = keep;
    for (int t = tid; t < keep; t += blockDim.x){
        unsigned long long key = keys[t];
        int m = (int)(key & 0xFFFFFFFFull);
        float dx = pin[m*3]-qx, dy = pin[m*3+1]-qy, dz = pin[m*3+2]-qz;
        float ux = dx*INV_R, uy = dy*INV_R, uz = dz*INV_R;
        float r2 = ux*ux + uy*uy + uz*uz;
        float t1 = 1.f - r2;
        float win = fminf(fmaxf(t1*t1*t1, 0.f), 1.f);
        float bx, by, bz;
        ball_to_cube(ux, uy, uz, bx, by, bz);
        float cxx = fminf(fmaxf((bx*0.5f+0.5f)*3.f, 0.f), 3.f);
        float cyy = fminf(fmaxf((by*0.5f+0.5f)*3.f, 0.f), 3.f);
        float czz = fminf(fmaxf((bz*0.5f+0.5f)*3.f, 0.f), 3.f);
        int c0x = min((int)floorf(cxx), 2);
        int c0y = min((int)floorf(cyy), 2);
        int c0z = min((int)floorf(czz), 2);
        float fx = cxx - (float)c0x, fy = cyy - (float)c0y, fz = czz - (float)c0z;
        sM[t] = m;
        sB[t] = (c0x*4 + c0y)*4 + c0z;
        float gx[2] = {1.f-fx, fx}, gy[2] = {1.f-fy, fy}, gz[2] = {1.f-fz, fz};
        int jj = 0;
        for (int i2=0;i2<2;i2++) for (int j2=0;j2<2;j2++) for (int l2=0;l2<2;l2++)
            sW8[t*8 + (jj++)] = gx[i2]*gy[j2]*gz[l2]*win;
    }
    for (int t = tid; t < 64; t += blockDim.x)
        skey[t] = (t < keep) ? (unsigned)((sB[t] << 6) | t) : 0xFFFFFFFFu;
    __syncthreads();
    for (int k = 2; k <= 64; k <<= 1){
        for (int j = k>>1; j > 0; j >>= 1){
            if (tid < 32){
                int i = ((tid & ~(j-1)) << 1) | (tid & (j-1));
                int ixj = i | j;
                bool asc = ((i & k) == 0);
                unsigned av = skey[i], bv = skey[ixj];
                if ((av > bv) == asc){ skey[i]=bv; skey[ixj]=av; }
            }
            __syncthreads();
        }
    }
    for (int t = tid; t < keep; t += blockDim.x){
        int s = (int)(skey[t] & 63u);
        idxO[n*64+t]  = sM[s];
        baseO[n*64+t] = sB[s];
#pragma unroll
        for (int j=0;j<8;j++) w8O[n*512 + t*8 + j] = sW8[s*8 + j];
    }
}

__constant__ int c_coff[8] = {0,1,4,5,16,17,20,21};

// ---------------- scatter layer0 fluid (F=9) ----------------
__global__ void scatter9(const float* __restrict__ feats,
                         const int* __restrict__ cnt, const int* __restrict__ nidx,
                         const int* __restrict__ nbase, const float* __restrict__ nw8,
                         float* __restrict__ A){
    __shared__ float planes[8*576];
    __shared__ float sfeat[64*9];
    __shared__ float sW[512];
    __shared__ int   sBase[64];
    __shared__ int   sIdx[64];
    int n = blockIdx.x, tid = threadIdx.x;
    int cn = cnt[n];
    for (int e = tid; e < 8*576; e += 96) planes[e] = 0.f;
    if (tid < cn){ sIdx[tid] = nidx[n*64+tid]; sBase[tid] = nbase[n*64+tid]; }
    for (int e = tid; e < cn*8; e += 96) sW[e] = nw8[n*512+e];
    __syncthreads();
    for (int e = tid; e < cn*9; e += 96){
        int k = e/9, f = e-k*9;
        sfeat[e] = feats[(size_t)sIdx[k]*9 + f];
    }
    __syncthreads();
    if (tid < 72){
        int j = tid/9, f = tid - j*9;
        int off = c_coff[j];
        float r = 0.f; int prevb = -1;
        for (int k = 0; k < cn; k++){
            int b = sBase[k];
            if (b != prevb){
                if (prevb >= 0) planes[j*576 + (prevb+off)*9 + f] += r;
                prevb = b; r = 0.f;
            }
            r += sW[k*8+j]*sfeat[k*9+f];
        }
        if (prevb >= 0) planes[j*576 + (prevb+off)*9 + f] += r;
    }
    __syncthreads();
    for (int e = tid; e < 576; e += 96){
        int l = e/9, f = e-l*9;
        int s = f/3, c = f-s*3;
        float v = 0.f;
#pragma unroll
        for (int j=0;j<8;j++) v += planes[j*576+e];
        A[(size_t)(n*3+s)*192 + l*3 + c] = v;
    }
}

// ---------------- scatter box (F=1) ----------------
__global__ void scatter1(const float* __restrict__ feats,
                         const int* __restrict__ cnt, const int* __restrict__ nidx,
                         const int* __restrict__ nbase, const float* __restrict__ nw8,
                         float* __restrict__ A){
    __shared__ float planes[8*8*64];
    __shared__ float sF[8*64];
    __shared__ float sW[8*512];
    __shared__ int   sBase[8*64];
    __shared__ int   sCn[8];
    int tid = threadIdx.x, nb = blockIdx.x;
    for (int e = tid; e < 8*8*64; e += 64) planes[e] = 0.f;
    for (int e = tid; e < 8*64; e += 64){
        int q = e>>6, k = e&63;
        int n = nb*8+q;
        if (k==0) sCn[q] = cnt[n];
        int cnq = cnt[n];
        if (k < cnq){ sBase[e] = nbase[n*64+k]; sF[e] = feats[nidx[n*64+k]]; }
    }
    for (int e = tid; e < 8*512; e += 64){
        int q = e>>9, r = e&511;
        sW[e] = nw8[(size_t)(nb*8+q)*512 + r];
    }
    __syncthreads();
    {
        int q = tid>>3, j = tid&7;
        int off = c_coff[j];
        int cnq = sCn[q];
        float r = 0.f; int prevb = -1;
        for (int k = 0; k < cnq; k++){
            int b = sBase[q*64+k];
            if (b != prevb){
                if (prevb >= 0) planes[(q*8+j)*64 + prevb+off] += r;
                prevb = b; r = 0.f;
            }
            r += sW[q*512 + k*8 + j]*sF[q*64+k];
        }
        if (prevb >= 0) planes[(q*8+j)*64 + prevb+off] += r;
    }
    __syncthreads();
    for (int e = tid; e < 512; e += 64){
        int q = e>>6, l = e&63;
        float v = 0.f;
#pragma unroll
        for (int j=0;j<8;j++) v += planes[(q*8+j)*64 + l];
        A[(size_t)(nb*8+q)*64 + l] = v;
    }
}

// ---------------- scatter (big): emits fp16 A rows [cellacc | relu(h)] ----------------
__global__ void scatter_big(const float* __restrict__ feats, int F, int C,
                            const int* __restrict__ cnt, const int* __restrict__ nidx,
                            const int* __restrict__ nbase, const float* __restrict__ nw8,
                            __half* __restrict__ Ah, int Kp){
    extern __shared__ float acc[];
    __shared__ int sIdx[64]; __shared__ int sBase[64]; __shared__ float sW[512];
    float4* acc4 = (float4*)acc;
    int n = blockIdx.x, tid = threadIdx.x, bd = blockDim.x;
    int F4 = F >> 2;
    int cn = cnt[n];
    for (int e = tid; e < 64*F4; e += bd) acc4[e] = make_float4(0.f,0.f,0.f,0.f);
    for (int e = tid; e < cn; e += bd){ sIdx[e] = nidx[n*64+e]; sBase[e] = nbase[n*64+e]; }
    for (int e = tid; e < cn*8; e += bd) sW[e] = nw8[n*512+e];
    __syncthreads();
    int f4 = tid;
    if (f4 < F4){
        float4 r[8];
        int prevb = -1;
        for (int k = 0; k < cn; k++){
            int b = sBase[k];
            if (b != prevb){
                if (prevb >= 0){
#pragma unroll
                    for (int j=0;j<8;j++){
                        int ai = (prevb + c_coff[j])*F4 + f4;
                        float4 t = acc4[ai];
                        t.x += r[j].x; t.y += r[j].y; t.z += r[j].z; t.w += r[j].w;
                        acc4[ai] = t;
                    }
                }
                prevb = b;
#pragma unroll
                for (int j=0;j<8;j++) r[j] = make_float4(0.f,0.f,0.f,0.f);
            }
            float4 fv = ((const float4*)(feats + (size_t)sIdx[k]*F))[f4];
            fv.x = fmaxf(fv.x,0.f); fv.y = fmaxf(fv.y,0.f);
            fv.z = fmaxf(fv.z,0.f); fv.w = fmaxf(fv.w,0.f);
#pragma unroll
            for (int j=0;j<8;j++){
                float w = sW[k*8+j];
                r[j].x += w*fv.x; r[j].y += w*fv.y; r[j].z += w*fv.z; r[j].w += w*fv.w;
            }
        }
        if (prevb >= 0){
#pragma unroll
            for (int j=0;j<8;j++){
                int ai = (prevb + c_coff[j])*F4 + f4;
                float4 t = acc4[ai];
                t.x += r[j].x; t.y += r[j].y; t.z += r[j].z; t.w += r[j].w;
                acc4[ai] = t;
            }
        }
    }
    __syncthreads();
    for (int e4 = tid; e4 < 64*F4; e4 += bd){
        int l = e4 / F4, fl = e4 - l*F4;
        int f = fl*4;
        int s = f / C, c = f - s*C;
        float4 v = acc4[e4];
        size_t base = (size_t)(n*3+s)*Kp + l*C + c;
        *(__half2*)(Ah+base)   = __floats2half2_rn(v.x, v.y);
        *(__half2*)(Ah+base+2) = __floats2half2_rn(v.z, v.w);
    }
    // append relu'd own-features (dense branch fused into GEMM)
    for (int e = tid; e < 3*C; e += bd){
        int s = e / C, c = e - s*C;
        float v = fmaxf(feats[(size_t)n*F + s*C + c], 0.f);
        Ah[(size_t)(n*3+s)*Kp + 64*C + c] = __float2half_rn(v);
    }
}

// ---------------- B': [kc ; wd] -> [64][Kp] fp16 (n-major, zero pad) ----------------
__global__ void convB(const float* __restrict__ kc, const float* __restrict__ wd,
                      int C, int Kp, __half* __restrict__ BhT){
    int e = blockIdx.x*blockDim.x + threadIdx.x;
    if (e >= 64*Kp) return;
    int n = e / Kp, k = e - n*Kp;
    float v = 0.f;
    if (k < 64*C) v = kc[(size_t)k*64 + n];
    else if (k < 64*C + C) v = wd[(size_t)(k - 64*C)*64 + n];
    BhT[e] = __float2half_rn(v);
}

// ---------------- fp16 MMA GEMM: C[M,64] = A[M,Kp] @ B[64,Kp]^T ----------------
__global__ __launch_bounds__(256) void gemm_mma(const __half* __restrict__ Ah,
                                                const __half* __restrict__ Bh,
                                                float* __restrict__ Cc, int M, int K){
    extern __shared__ __half sm[];
    const int RS = 40;
    const int OFF_B = 128*RS;       // 5120
    const int BUFSZ = 192*RS;       // 7680 halves per buffer
    int tid = threadIdx.x;
    int bm = blockIdx.x*128;
    int kLen = K / gridDim.y;
    int kBeg = blockIdx.y*kLen;
    int T = kLen >> 5;
    float* Cout = Cc + (size_t)blockIdx.y * M * 64;

    int arow = tid >> 1, ahalf = tid & 1;
    const __half* AG = Ah + (size_t)(bm+arow)*K + kBeg + ahalf*16;
    int brow = tid >> 2, bq = tid & 3;
    const __half* BG = Bh + (size_t)brow*K + kBeg + bq*8;

    uint32_t sbase = smem_u32(sm);
    int wid = tid >> 5, lane = tid & 31;
    int wm = wid & 3, wn = wid >> 2;

    uint4 ra0, ra1, rb;
    ra0 = *(const uint4*)(AG);  ra1 = *(const uint4*)(AG + 8);
    rb  = *(const uint4*)(BG);
    {
        __half* buf = sm;
        *(uint4*)(buf + arow*RS + ahalf*16)     = ra0;
        *(uint4*)(buf + arow*RS + ahalf*16 + 8) = ra1;
        *(uint4*)(buf + OFF_B + brow*RS + bq*8) = rb;
    }
    __syncthreads();

    float acc[2][4][4];
#pragma unroll
    for (int mt=0;mt<2;mt++)
#pragma unroll
        for (int nt=0;nt<4;nt++)
#pragma unroll
            for (int q=0;q<4;q++) acc[mt][nt][q] = 0.f;

    for (int t = 0; t < T; t++){
        if (t+1 < T){
            ra0 = *(const uint4*)(AG + (size_t)(t+1)*32);
            ra1 = *(const uint4*)(AG + (size_t)(t+1)*32 + 8);
            rb  = *(const uint4*)(BG + (size_t)(t+1)*32);
        }
        uint32_t bufo = (uint32_t)((t & 1) * BUFSZ) * 2;
#pragma unroll
        for (int ks = 0; ks < 2; ks++){
            int k0 = ks*16;
            uint32_t af[2][4];
#pragma unroll
            for (int mt=0;mt<2;mt++){
                int row = wm*32 + mt*16 + (lane & 15);
                int col = k0 + (lane >> 4)*8;
                uint32_t addr = sbase + bufo + (uint32_t)(row*RS + col)*2;
                ldsm_x4(af[mt][0], af[mt][1], af[mt][2], af[mt][3], addr);
            }
            uint32_t bf[4][2];
#pragma unroll
            for (int nt=0;nt<4;nt++){
                int row = wn*32 + nt*8 + (lane & 7);
                int col = k0 + ((lane >> 3) & 1)*8;
                uint32_t addr = sbase + bufo + (uint32_t)(OFF_B + row*RS + col)*2;
                ldsm_x2(bf[nt][0], bf[nt][1], addr);
            }
#pragma unroll
            for (int mt=0;mt<2;mt++)
#pragma unroll
                for (int nt=0;nt<4;nt++)
                    mma_f16(acc[mt][nt], af[mt], bf[nt]);
        }
        if (t+1 < T){
            __half* buf = sm + ((t+1) & 1) * BUFSZ;
            *(uint4*)(buf + arow*RS + ahalf*16)     = ra0;
            *(uint4*)(buf + arow*RS + ahalf*16 + 8) = ra1;
            *(uint4*)(buf + OFF_B + brow*RS + bq*8) = rb;
            __syncthreads();
        }
    }
#pragma unroll
    for (int mt=0;mt<2;mt++){
#pragma unroll
        for (int nt=0;nt<4;nt++){
            int r0 = bm + wm*32 + mt*16 + (lane >> 2);
            int c0 = wn*32 + nt*8 + (lane & 3)*2;
            if (r0 < M)     *(float2*)&Cout[(size_t)r0*64 + c0]     = make_float2(acc[mt][nt][0], acc[mt][nt][1]);
            if (r0+8 < M)   *(float2*)&Cout[(size_t)(r0+8)*64 + c0] = make_float2(acc[mt][nt][2], acc[mt][nt][3]);
        }
    }
}

// ---------------- fp32 GEMM N=32 (layer 0) ----------------
__global__ void gemm32(const float* __restrict__ A, const float* __restrict__ B,
                       float* __restrict__ Cc, int M, int N, int K){
    __shared__ float As[16][64];
    __shared__ float Bs[16][64];
    int tid = threadIdx.x;
    int bm = blockIdx.x * 64;
    int tm = tid >> 4, tn = tid & 15;
    float accv[4][4] = {};
    int arow = bm + (tid >> 2);
    int akq  = (tid & 3) * 4;
    int brow = tid >> 4;
    int bcol = (tid & 15) * 4;
    for (int k0 = 0; k0 < K; k0 += 16){
        float4 a4 = make_float4(0.f,0.f,0.f,0.f);
        if (arow < M) a4 = *(const float4*)(A + (size_t)arow*K + k0 + akq);
        float4 b4 = make_float4(0.f,0.f,0.f,0.f);
        if (bcol < N) b4 = *(const float4*)(B + (size_t)(k0+brow)*N + bcol);
        __syncthreads();
        int lr = tid >> 2;
        As[akq+0][lr] = a4.x; As[akq+1][lr] = a4.y; As[akq+2][lr] = a4.z; As[akq+3][lr] = a4.w;
        *(float4*)&Bs[brow][bcol] = b4;
        __syncthreads();
#pragma unroll
        for (int kk = 0; kk < 16; kk++){
            float4 av = *(const float4*)&As[kk][tm*4];
            float4 bv = *(const float4*)&Bs[kk][tn*4];
            float ar[4] = {av.x, av.y, av.z, av.w};
            float brr[4] = {bv.x, bv.y, bv.z, bv.w};
#pragma unroll
            for (int i=0;i<4;i++)
#pragma unroll
                for (int j=0;j<4;j++) accv[i][j] += ar[i]*brr[j];
        }
    }
#pragma unroll
    for (int i=0;i<4;i++){
        int r = bm + tm*4 + i;
        if (r >= M) continue;
#pragma unroll
        for (int j=0;j<4;j++){
            int c = tn*4 + j;
            if (c < N) Cc[(size_t)r*N + c] = accv[i][j];
        }
    }
}

// ---------------- fused layer-4 dot: oc+od = A(fp16)[M,K'] @ [kc;wd] ----------------
__global__ void dotn_f16(const __half* __restrict__ Ah,
                         const float* __restrict__ kcB, const float* __restrict__ wdB,
                         int C, float* __restrict__ Cc, int M, int Kp){
    extern __shared__ float sBv[];
    int tid = threadIdx.x;
    int Kc = 64*C, Kt = Kc + C;
    for (int i = tid; i < Kc*3; i += blockDim.x) sBv[i] = kcB[i];
    for (int i = tid; i < C*3; i += blockDim.x) sBv[Kc*3 + i] = wdB[i];
    __syncthreads();
    int w = tid >> 5, lane = tid & 31;
    int r = blockIdx.x * 8 + w;
    if (r >= M) return;
    float a0=0.f, a1=0.f, a2=0.f;
    const __half* ap = Ah + (size_t)r*Kp;
    for (int k = lane*2; k < Kt; k += 64){
        __half2 h2 = *(const __half2*)(ap + k);
        float av0 = __half2float(h2.x);
        float av1 = __half2float(h2.y);
        a0 += av0 * sBv[k*3+0] + av1 * sBv[(k+1)*3+0];
        a1 += av0 * sBv[k*3+1] + av1 * sBv[(k+1)*3+1];
        a2 += av0 * sBv[k*3+2] + av1 * sBv[(k+1)*3+2];
    }
    for (int off=16; off; off>>=1){
        a0 += __shfl_down_sync(0xffffffffu, a0, off);
        a1 += __shfl_down_sync(0xffffffffu, a1, off);
        a2 += __shfl_down_sync(0xffffffffu, a2, off);
    }
    if (lane == 0){
        Cc[(size_t)r*3+0] = a0;
        Cc[(size_t)r*3+1] = a1;
        Cc[(size_t)r*3+2] = a2;
    }
}

// ---------------- elementwise ----------------
__global__ void combine0_kernel(const float* __restrict__ co, const float* __restrict__ cf,
                                const float* __restrict__ feat0,
                                const float* __restrict__ b0o, const float* __restrict__ b0f,
                                const float* __restrict__ wdf, const float* __restrict__ bdf,
                                float* __restrict__ out){
    int e = blockIdx.x*blockDim.x + threadIdx.x;
    if (e >= 9000*96) return;
    int row = e / 96, o = e - row*96;
    int n = row / 3;
    float v;
    if (o < 32) v = co[n*32+o] + b0o[o];
    else if (o < 64) v = cf[(size_t)row*32 + (o-32)] + b0f[o-32];
    else {
        int oo = o - 64;
        v = bdf[oo];
        for (int c=0;c<3;c++) v += feat0[row*3+c]*wdf[c*32+oo];
    }
    out[e] = v;
}

__global__ void combine_kernel(const float* __restrict__ oc, int nsplit,
                               const float* __restrict__ bc, const float* __restrict__ bd,
                               const float* __restrict__ prev, float* __restrict__ out, int C){
    int e = blockIdx.x*blockDim.x + threadIdx.x;
    if (e >= 9000*C) return;
    int o = e % C;
    float v = bc[o] + bd[o];
    for (int j = 0; j < nsplit; j++) v += oc[(size_t)j*9000*64 + e];
    if (prev) v += prev[e];
    out[e] = v;
}

__global__ void final_kernel(const float* __restrict__ out4, const float* __restrict__ p1,
                             const float* __restrict__ p0, float* __restrict__ dout){
    int e = blockIdx.x*blockDim.x + threadIdx.x;
    if (e >= NF*3) return;
    int n = e/3, d = e - n*3;
    float pc0 = out4[(n*3+0)*3+d] * 0.25f * (1.0f/16.0f);
    float pc1 = out4[(n*3+1)*3+d] * 0.25f;
    float pc2 = out4[(n*3+2)*3+d] * 0.25f;
    float p_c = p1[e] + pc0;
    dout[e] = p_c;
    dout[9000 + e] = (p_c - p0[e]) / 0.1f;
    dout[18000 + n*6 + d]     = pc1;
    dout[18000 + n*6 + 3 + d] = pc2;
}

// ---------------- launch ----------------
extern "C" void kernel_launch(void* const* d_in, const int* in_sizes, int n_in,
                              void* d_out, int out_size){
    const float* v0e  = (const float*)d_in[1];
    const float* p0   = (const float*)d_in[2];
    const float* v0   = (const float*)d_in[3];
    const float* a    = (const float*)d_in[4];
    const float* other= (const float*)d_in[5];
    const float* box  = (const float*)d_in[6];
    const float* boxf = (const float*)d_in[7];
    const float* bmask= (const float*)d_in[9];
    const float* k0f  = (const float*)d_in[10];
    const float* b0f  = (const float*)d_in[11];
    const float* k0o  = (const float*)d_in[12];
    const float* b0o  = (const float*)d_in[13];
    const float* wdf  = (const float*)d_in[14];
    const float* bdf  = (const float*)d_in[15];
    const float *kc[4], *bcp[4], *wd[4], *bdp[4];
    if (in_sizes[18] == 262144){
        for (int i=0;i<4;i++){
            kc[i]=(const float*)d_in[16+2*i]; bcp[i]=(const float*)d_in[17+2*i];
            wd[i]=(const float*)d_in[24+2*i]; bdp[i]=(const float*)d_in[25+2*i];
        }
    } else {
        for (int i=0;i<4;i++){
            kc[i]=(const float*)d_in[16+4*i]; bcp[i]=(const float*)d_in[17+4*i];
            wd[i]=(const float*)d_in[18+4*i]; bdp[i]=(const float*)d_in[19+4*i];
        }
    }
    float* dout = (float*)d_out;

    float *p1, *feat0, *A0, *Abox, *cfb, *cob, *ocb, *o1, *o2, *fw8, *bw8;
    __half *Ahp, *Bhp;
    int *fcnt, *fidx, *fbase, *bcnt, *bidx, *bbase;
    cudaGetSymbolAddress((void**)&p1, g_p1);
    cudaGetSymbolAddress((void**)&feat0, g_feat0);
    cudaGetSymbolAddress((void**)&A0, g_A0);
    cudaGetSymbolAddress((void**)&Abox, g_Abox);
    cudaGetSymbolAddress((void**)&Ahp, g_Ah);
    cudaGetSymbolAddress((void**)&Bhp, g_Bh);
    cudaGetSymbolAddress((void**)&cfb, g_cf);
    cudaGetSymbolAddress((void**)&cob, g_co);
    cudaGetSymbolAddress((void**)&ocb, g_oc);
    cudaGetSymbolAddress((void**)&o1, g_out1);
    cudaGetSymbolAddress((void**)&o2, g_out2);
    cudaGetSymbolAddress((void**)&fw8, g_fw8);
    cudaGetSymbolAddress((void**)&bw8, g_bw8);
    cudaGetSymbolAddress((void**)&fcnt, g_fcnt);
    cudaGetSymbolAddress((void**)&fidx, g_fidx);
    cudaGetSymbolAddress((void**)&fbase, g_fbase);
    cudaGetSymbolAddress((void**)&bcnt, g_bcnt);
    cudaGetSymbolAddress((void**)&bidx, g_bidx);
    cudaGetSymbolAddress((void**)&bbase, g_bbase);

    cudaFuncSetAttribute(scatter_big, cudaFuncAttributeMaxDynamicSharedMemorySize, 80000);
    cudaFuncSetAttribute(gemm_mma,    cudaFuncAttributeMaxDynamicSharedMemorySize, 31000);
    cudaFuncSetAttribute(dotn_f16,    cudaFuncAttributeMaxDynamicSharedMemorySize, 50000);

    int Kp[4]       = {6272, 4160, 4160, 4160};
    size_t BOff[3]  = {0, (size_t)64*6272, (size_t)64*6272 + (size_t)64*4160};
    int Cin[4]      = {96, 64, 64, 64};

    // weight-only conversions first (off the data-dependent chain)
    convB<<<(64*6272+255)/256, 256>>>(kc[0], wd[0], 96, 6272, Bhp + BOff[0]);
    convB<<<(64*4160+255)/256, 256>>>(kc[1], wd[1], 64, 4160, Bhp + BOff[1]);
    convB<<<(64*4160+255)/256, 256>>>(kc[2], wd[2], 64, 4160, Bhp + BOff[2]);

    prep_kernel<<<(NF+127)/128, 128>>>(p0, v0, a, other, v0e, p1, feat0, dout + 36000);
    neigh_kernel<<<NF, 256>>>(p1, NF, p1, nullptr, 1, fcnt, fidx, fbase, fw8);
    neigh_kernel<<<NF, 256>>>(box, NB, p1, bmask, 0, bcnt, bidx, bbase, bw8);

    // layer 0
    scatter9<<<NF, 96>>>(feat0, fcnt, fidx, fbase, fw8, A0);
    gemm32<<<(9000+63)/64, 256>>>(A0, k0f, cfb, 9000, 32, 192);
    scatter1<<<NF/8, 64>>>(boxf, bcnt, bidx, bbase, bw8, Abox);
    gemm32<<<(3000+63)/64, 256>>>(Abox, k0o, cob, 3000, 32, 64);
    combine0_kernel<<<(9000*96+255)/256, 256>>>(cob, cfb, feat0, b0o, b0f, wdf, bdf, o1);

    float* cur = o1; float* nxt = o2;
    for (int i=0;i<4;i++){
        int ci = Cin[i];
        int F = 3*ci, F4 = F/4;
        int bD = ((F4 + 31)/32)*32;
        scatter_big<<<NF, bD, (size_t)64*F*4>>>(cur, F, ci, fcnt, fidx, fbase, fw8, Ahp, Kp[i]);
        if (i < 3){
            gemm_mma<<<dim3(71,2), 256, 30720>>>(Ahp, Bhp + BOff[i], ocb, 9000, Kp[i]);
            combine_kernel<<<(9000*64+255)/256, 256>>>(ocb, 2,
                bcp[i], bdp[i], (i==1||i==2) ? cur : nullptr, nxt, 64);
        } else {
            dotn_f16<<<(9000+7)/8, 256, (size_t)4160*3*4>>>(Ahp, kc[3], wd[3], 64, ocb, 9000, Kp[3]);
            combine_kernel<<<(27000+255)/256, 256>>>(ocb, 1,
                bcp[3], bdp[3], nullptr, nxt, 3);
        }
        float* t = cur; cur = nxt; nxt = t;
    }
    final_kernel<<<(NF*3+255)/256, 256>>>(cur, p1, p0, dout);
}